// round 6
// baseline (speedup 1.0000x reference)
#include <cuda_runtime.h>
#include <cuda_fp16.h>
#include <math_constants.h>
#include <cstdint>

// Problem dimensions (deterministic from setup_inputs)
#define BNUM 4
#define CCH 128          // channels
#define HF 128           // feature map height
#define WF 128           // feature map width
#define NV 10475         // vertices
#define NPTS 200000      // gaussians
#define KB 20            // bary rows
#define IMH 512
#define IMW 512
#define HWIMG (IMH*IMW)
#define HWF (HF*WF)
#define C8 (CCH / 8)     // uint4 (8 halves) per pixel = 16
#define NPT (BNUM * NPTS)
#define NBINS (BNUM * HWF)   // 65536 pixel bins

// Scratch (static device globals -- no allocation allowed)
__device__ uint4  g_fmTh[(size_t)BNUM * HWF * C8];  // 16 MB fp16 transposed map (B,Hf,Wf,C)
__device__ float  g_depth[BNUM * HWIMG];            // 4 MB depth maps
__device__ int4   g_off [NPT];                      // per-point corner offsets (orig order)
__device__ float4 g_wt  [NPT];                      // per-point corner weights (orig order)
__device__ int4   g_soff[NPT];                      // sorted-order offsets
__device__ float4 g_swt [NPT];                      // sorted-order weights
__device__ int    g_ord [NPT];                      // sorted slot -> original point idx
__device__ int    g_hist[NBINS];                    // pixel-bin histogram
__device__ int    g_cursor[NBINS];                  // bin write cursors (prefix sums)

// ---------------------------------------------------------------------------
// Kernel 1: transpose + fp16-convert feature map (B,C,Hf*Wf) -> (B,Hf*Wf,C)
//           AND init depth maps (+inf) AND zero histogram (fused inits).
// ---------------------------------------------------------------------------
__global__ void transpose_k(const float* __restrict__ fm) {
    __shared__ float tile[32][33];
    const int b  = blockIdx.z;
    const int p0 = blockIdx.x * 32;   // pixel base (Hf*Wf dim)
    const int c0 = blockIdx.y * 32;   // channel base
    const float* src = fm + (size_t)b * CCH * HWF;
    __half2* dst = reinterpret_cast<__half2*>(g_fmTh) + (size_t)b * HWF * (CCH / 2);

    const int tid = threadIdx.y * 32 + threadIdx.x;   // 0..255
    const int bid = (blockIdx.z * gridDim.y + blockIdx.y) * gridDim.x + blockIdx.x;
    const int gi  = bid * 256 + tid;

    // fused depth-map init (262144 float4) and histogram zero (16384 int4)
    if (gi < BNUM * HWIMG / 4) {
        reinterpret_cast<float4*>(g_depth)[gi] =
            make_float4(CUDART_INF_F, CUDART_INF_F, CUDART_INF_F, CUDART_INF_F);
    }
    if (gi < NBINS / 4) {
        reinterpret_cast<int4*>(g_hist)[gi] = make_int4(0, 0, 0, 0);
    }

    // read: coalesced along pixel dim
    {
        const int x = p0 + threadIdx.x;
        for (int j = threadIdx.y; j < 32; j += 8)
            tile[j][threadIdx.x] = src[(size_t)(c0 + j) * HWF + x];
    }
    __syncthreads();
    // write: 32 pixels x 16 half2 (32 channels) per tile = 512 half2
    for (int e = tid; e < 32 * 16; e += 256) {
        const int pix = e >> 4;
        const int ch2 = e & 15;
        __half2 h = __floats2half2_rn(tile[2 * ch2][pix], tile[2 * ch2 + 1][pix]);
        dst[(size_t)(p0 + pix) * (CCH / 2) + (c0 / 2) + ch2] = h;
    }
}

// ---------------------------------------------------------------------------
// Kernel 2: scatter-min vertex depths.  z > 0 so int-compare == float-compare.
// ---------------------------------------------------------------------------
__global__ void scatter_k(const float* __restrict__ v2d, const float* __restrict__ v3d) {
    const int i = blockIdx.x * blockDim.x + threadIdx.x;
    if (i >= BNUM * NV) return;
    const float xf = rintf(v2d[2 * i]);       // round-half-even, matches jnp.round
    const float yf = rintf(v2d[2 * i + 1]);
    const int xi = (int)xf, yi = (int)yf;
    if (xi < 0 || xi >= IMW || yi < 0 || yi >= IMH) return;
    const int b = i / NV;
    const float z = v3d[3 * i + 2];
    atomicMin(reinterpret_cast<int*>(&g_depth[b * HWIMG + yi * IMW + xi]),
              __float_as_int(z));
}

// ---------------------------------------------------------------------------
// Kernel 3: per-point geometry + bilinear params + pixel-bin histogram.
// ---------------------------------------------------------------------------
__global__ void points_k(const float* __restrict__ v2d, const float* __restrict__ v3d,
                         const int*   __restrict__ parents, const float* __restrict__ bary,
                         float* __restrict__ out_vw, float* __restrict__ out_c3) {
    const int idx = blockIdx.x * blockDim.x + threadIdx.x;
    if (idx >= NPT) return;
    const int b = idx / NPTS;
    const int n = idx - b * NPTS;
    const int kk = n % KB;

    const float w0 = __ldg(&bary[kk * 3 + 0]);
    const float w1 = __ldg(&bary[kk * 3 + 1]);
    const float w2 = __ldg(&bary[kk * 3 + 2]);

    const int p0 = __ldg(&parents[n * 3 + 0]);
    const int p1 = __ldg(&parents[n * 3 + 1]);
    const int p2 = __ldg(&parents[n * 3 + 2]);

    const float* v2b = v2d + (size_t)b * NV * 2;
    const float* v3b = v3d + (size_t)b * NV * 3;

    const float2 a2 = *reinterpret_cast<const float2*>(v2b + 2 * p0);
    const float2 b2 = *reinterpret_cast<const float2*>(v2b + 2 * p1);
    const float2 c2 = *reinterpret_cast<const float2*>(v2b + 2 * p2);
    const float cx = w0 * a2.x + w1 * b2.x + w2 * c2.x;
    const float cy = w0 * a2.y + w1 * b2.y + w2 * c2.y;

    const float ax = v3b[3 * p0], ay = v3b[3 * p0 + 1], az = v3b[3 * p0 + 2];
    const float bx = v3b[3 * p1], by = v3b[3 * p1 + 1], bz = v3b[3 * p1 + 2];
    const float gx = v3b[3 * p2], gy = v3b[3 * p2 + 1], gz = v3b[3 * p2 + 2];

    const float c3x = w0 * ax + w1 * bx + w2 * gx;
    const float c3y = w0 * ay + w1 * by + w2 * gy;
    const float c3z = w0 * az + w1 * bz + w2 * gz;

    // face normal
    const float e1x = bx - ax, e1y = by - ay, e1z = bz - az;
    const float e2x = gx - ax, e2y = gy - ay, e2z = gz - az;
    float nx = e1y * e2z - e1z * e2y;
    float ny = e1z * e2x - e1x * e2z;
    float nz = e1x * e2y - e1y * e2x;
    const float nrm = sqrtf(nx * nx + ny * ny + nz * nz) + 1e-8f;
    nx /= nrm; ny /= nrm; nz /= nrm;

    const float cl = sqrtf(c3x * c3x + c3y * c3y + c3z * c3z) + 1e-8f;
    const float vx = -c3x / cl, vy = -c3y / cl, vz = -c3z / cl;
    const float ang = fmaxf(nx * vx + ny * vy + nz * vz, 0.0f);

    // depth-based visibility
    const int xcd = min(max((int)rintf(cx), 0), IMW - 1);
    const int ycd = min(max((int)rintf(cy), 0), IMH - 1);
    const float dsamp = g_depth[b * HWIMG + ycd * IMW + xcd];
    const bool vis = (c3z <= dsamp + 1e-3f) || isinf(dsamp);

    out_vw[idx] = vis ? ang : 0.0f;
    out_c3[(size_t)idx * 3 + 0] = c3x;
    out_c3[(size_t)idx * 3 + 1] = c3y;
    out_c3[(size_t)idx * 3 + 2] = c3z;

    // grid-sample pixel coords (same formula chain as reference)
    const float gxn = cx / (float)(IMW - 1) * 2.0f - 1.0f;
    const float gyn = cy / (float)(IMH - 1) * 2.0f - 1.0f;
    const float px = (gxn + 1.0f) * 0.5f * (float)(WF - 1);
    const float py = (gyn + 1.0f) * 0.5f * (float)(HF - 1);

    // bilinear params
    const float x0f = floorf(px), y0f = floorf(py);
    const float wx = px - x0f, wy = py - y0f;
    const int x0 = (int)x0f, y0 = (int)y0f;

    const bool ix0 = (x0 >= 0) && (x0 < WF);
    const bool ix1 = (x0 + 1 >= 0) && (x0 + 1 < WF);
    const bool iy0 = (y0 >= 0) && (y0 < HF);
    const bool iy1 = (y0 + 1 >= 0) && (y0 + 1 < HF);

    const float w00 = (1.0f - wx) * (1.0f - wy) * (float)(ix0 && iy0);
    const float w10 = wx * (1.0f - wy)          * (float)(ix1 && iy0);
    const float w01 = (1.0f - wx) * wy          * (float)(ix0 && iy1);
    const float w11 = wx * wy                   * (float)(ix1 && iy1);

    const int xc0 = min(max(x0, 0), WF - 1);
    const int xc1 = min(max(x0 + 1, 0), WF - 1);
    const int yc0 = min(max(y0, 0), HF - 1);
    const int yc1 = min(max(y0 + 1, 0), HF - 1);

    const int bin = b * HWF + yc0 * WF + xc0;     // pixel bin (also offset base)
    g_off[idx] = make_int4(bin * C8,
                           (b * HWF + yc0 * WF + xc1) * C8,
                           (b * HWF + yc1 * WF + xc0) * C8,
                           (b * HWF + yc1 * WF + xc1) * C8);
    g_wt[idx] = make_float4(w00, w10, w01, w11);
    atomicAdd(&g_hist[bin], 1);
}

// ---------------------------------------------------------------------------
// Kernel 4: exclusive prefix sum over 65536 bins -> g_cursor. Single block.
// ---------------------------------------------------------------------------
__global__ void __launch_bounds__(1024) prefix_k() {
    __shared__ int ssum[1024];
    const int t = threadIdx.x;
    const int base = t * (NBINS / 1024);   // 64 bins per thread
    int s = 0;
    for (int i = 0; i < NBINS / 1024; i++) s += g_hist[base + i];
    ssum[t] = s;
    __syncthreads();
    // Hillis-Steele inclusive scan
    for (int off = 1; off < 1024; off <<= 1) {
        int v = ssum[t];
        int u = (t >= off) ? ssum[t - off] : 0;
        __syncthreads();
        ssum[t] = v + u;
        __syncthreads();
    }
    int run = (t == 0) ? 0 : ssum[t - 1];   // exclusive
    for (int i = 0; i < NBINS / 1024; i++) {
        const int h = g_hist[base + i];
        g_cursor[base + i] = run;
        run += h;
    }
}

// ---------------------------------------------------------------------------
// Kernel 5: permute params into pixel-sorted order (counting-sort scatter).
// Slot assignment within a bin is atomic (nondeterministic order) but the
// final output is written back to original indices, so results are identical.
// ---------------------------------------------------------------------------
__global__ void perm_k() {
    const int idx = blockIdx.x * blockDim.x + threadIdx.x;
    if (idx >= NPT) return;
    const int4 o = g_off[idx];
    const int bin = o.x >> 4;               // /C8 recovers b*HWF + y0*WF + x0
    const int slot = atomicAdd(&g_cursor[bin], 1);
    g_soff[slot] = o;
    g_swt[slot]  = g_wt[idx];
    g_ord[slot]  = idx;
}

// ---------------------------------------------------------------------------
// Kernel 6: bilinear sampling in pixel-sorted order. 16 lanes / point.
// Warp's 2 points almost always share a pixel -> corner loads broadcast and
// stay L1-hot across warps; param reads fully sequential. Output scattered by
// original index in 512B blocks (full sectors), streaming stores.
// ---------------------------------------------------------------------------
__global__ void __launch_bounds__(256) sample_k(float* __restrict__ out_feats) {
    const unsigned t  = blockIdx.x * blockDim.x + threadIdx.x;
    const unsigned gw = t >> 4;                 // sorted slot (16 lanes per point)
    if (gw >= (unsigned)NPT) return;
    const int lane = t & 15;

    const int4   o   = g_soff[gw];
    const float4 w   = g_swt[gw];
    const int    idx = g_ord[gw];

    const uint4 f00 = __ldg(&g_fmTh[o.x + lane]);
    const uint4 f10 = __ldg(&g_fmTh[o.y + lane]);
    const uint4 f01 = __ldg(&g_fmTh[o.z + lane]);
    const uint4 f11 = __ldg(&g_fmTh[o.w + lane]);

    const __half2 w00 = __float2half2_rn(w.x);
    const __half2 w10 = __float2half2_rn(w.y);
    const __half2 w01 = __float2half2_rn(w.z);
    const __half2 w11 = __float2half2_rn(w.w);

    const __half2* h00 = reinterpret_cast<const __half2*>(&f00);
    const __half2* h10 = reinterpret_cast<const __half2*>(&f10);
    const __half2* h01 = reinterpret_cast<const __half2*>(&f01);
    const __half2* h11 = reinterpret_cast<const __half2*>(&f11);

    float2 r[4];
#pragma unroll
    for (int k = 0; k < 4; k++) {
        __half2 acc = __hmul2(h00[k], w00);
        acc = __hfma2(h10[k], w10, acc);
        acc = __hfma2(h01[k], w01, acc);
        acc = __hfma2(h11[k], w11, acc);
        r[k] = __half22float2(acc);
    }

    float4* outp = reinterpret_cast<float4*>(out_feats) + (size_t)idx * (CCH / 4) + lane * 2;
    __stcs(outp,     make_float4(r[0].x, r[0].y, r[1].x, r[1].y));
    __stcs(outp + 1, make_float4(r[2].x, r[2].y, r[3].x, r[3].y));
}

// ---------------------------------------------------------------------------
extern "C" void kernel_launch(void* const* d_in, const int* in_sizes, int n_in,
                              void* d_out, int out_size) {
    const float* fm      = (const float*)d_in[0];
    const float* v2d     = (const float*)d_in[1];
    const float* v3d     = (const float*)d_in[2];
    const int*   parents = (const int*)  d_in[3];
    const float* bary    = (const float*)d_in[4];
    (void)in_sizes; (void)n_in; (void)out_size;

    float* out       = (float*)d_out;
    float* out_feats = out;                                    // (B,N,C)
    float* out_vw    = out + (size_t)BNUM * NPTS * CCH;        // (B,N)
    float* out_c3    = out_vw + (size_t)BNUM * NPTS;           // (B,N,3)

    transpose_k<<<dim3(HWF / 32, CCH / 32, BNUM), dim3(32, 8)>>>(fm);  // + inits
    scatter_k<<<(BNUM * NV + 255) / 256, 256>>>(v2d, v3d);
    points_k<<<(NPT + 255) / 256, 256>>>(v2d, v3d, parents, bary, out_vw, out_c3);
    prefix_k<<<1, 1024>>>();
    perm_k<<<(NPT + 255) / 256, 256>>>();
    sample_k<<<((size_t)NPT * 16 + 255) / 256, 256>>>(out_feats);
}

// round 7
// speedup vs baseline: 1.5935x; 1.5935x over previous
#include <cuda_runtime.h>
#include <cuda_fp16.h>
#include <math_constants.h>
#include <cstdint>

// Problem dimensions (deterministic from setup_inputs)
#define BNUM 4
#define CCH 128          // channels
#define HF 128           // feature map height
#define WF 128           // feature map width
#define NV 10475         // vertices
#define NPTS 200000      // gaussians
#define KB 20            // bary rows
#define IMH 512
#define IMW 512
#define HWIMG (IMH*IMW)
#define HWF (HF*WF)
#define C8 (CCH / 8)     // uint4 (8 halves) per pixel = 16
#define NPT (BNUM * NPTS)
#define NBINS (BNUM * HWF)   // 65536 pixel bins
#define NSBLK 64             // scan blocks (1024 bins each)

// Scratch (static device globals -- no allocation allowed)
__device__ uint4  g_fmTh[(size_t)BNUM * HWF * C8];  // 16 MB fp16 transposed map (B,Hf,Wf,C)
__device__ float  g_depth[BNUM * HWIMG];            // 4 MB depth maps
__device__ int4   g_off [NPT];                      // per-point corner offsets (orig order)
__device__ float4 g_wt  [NPT];                      // per-point corner weights (orig order)
__device__ int4   g_soff[NPT];                      // sorted-order offsets
__device__ float4 g_swt [NPT];                      // sorted-order weights
__device__ int    g_ord [NPT];                      // sorted slot -> original point idx
__device__ int    g_hist[NBINS];                    // pixel-bin histogram
__device__ int    g_cursor[NBINS];                  // block-local exclusive scan + cursors
__device__ int    g_bsum[NSBLK];                    // per-scan-block totals -> exclusive offsets

// ---------------------------------------------------------------------------
// Kernel 1: transpose + fp16-convert feature map (B,C,Hf*Wf) -> (B,Hf*Wf,C)
//           AND init depth maps (+inf) AND zero histogram (fused inits).
// ---------------------------------------------------------------------------
__global__ void transpose_k(const float* __restrict__ fm) {
    __shared__ float tile[32][33];
    const int b  = blockIdx.z;
    const int p0 = blockIdx.x * 32;   // pixel base (Hf*Wf dim)
    const int c0 = blockIdx.y * 32;   // channel base
    const float* src = fm + (size_t)b * CCH * HWF;
    __half2* dst = reinterpret_cast<__half2*>(g_fmTh) + (size_t)b * HWF * (CCH / 2);

    const int tid = threadIdx.y * 32 + threadIdx.x;   // 0..255
    const int bid = (blockIdx.z * gridDim.y + blockIdx.y) * gridDim.x + blockIdx.x;
    const int gi  = bid * 256 + tid;

    // fused depth-map init (262144 float4) and histogram zero (16384 int4)
    if (gi < BNUM * HWIMG / 4) {
        reinterpret_cast<float4*>(g_depth)[gi] =
            make_float4(CUDART_INF_F, CUDART_INF_F, CUDART_INF_F, CUDART_INF_F);
    }
    if (gi < NBINS / 4) {
        reinterpret_cast<int4*>(g_hist)[gi] = make_int4(0, 0, 0, 0);
    }

    // read: coalesced along pixel dim
    {
        const int x = p0 + threadIdx.x;
        for (int j = threadIdx.y; j < 32; j += 8)
            tile[j][threadIdx.x] = src[(size_t)(c0 + j) * HWF + x];
    }
    __syncthreads();
    // write: 32 pixels x 16 half2 (32 channels) per tile = 512 half2
    for (int e = tid; e < 32 * 16; e += 256) {
        const int pix = e >> 4;
        const int ch2 = e & 15;
        __half2 h = __floats2half2_rn(tile[2 * ch2][pix], tile[2 * ch2 + 1][pix]);
        dst[(size_t)(p0 + pix) * (CCH / 2) + (c0 / 2) + ch2] = h;
    }
}

// ---------------------------------------------------------------------------
// Kernel 2: scatter-min vertex depths.  z > 0 so int-compare == float-compare.
// ---------------------------------------------------------------------------
__global__ void scatter_k(const float* __restrict__ v2d, const float* __restrict__ v3d) {
    const int i = blockIdx.x * blockDim.x + threadIdx.x;
    if (i >= BNUM * NV) return;
    const float xf = rintf(v2d[2 * i]);       // round-half-even, matches jnp.round
    const float yf = rintf(v2d[2 * i + 1]);
    const int xi = (int)xf, yi = (int)yf;
    if (xi < 0 || xi >= IMW || yi < 0 || yi >= IMH) return;
    const int b = i / NV;
    const float z = v3d[3 * i + 2];
    atomicMin(reinterpret_cast<int*>(&g_depth[b * HWIMG + yi * IMW + xi]),
              __float_as_int(z));
}

// ---------------------------------------------------------------------------
// Kernel 3: per-point geometry + bilinear params + pixel-bin histogram.
// ---------------------------------------------------------------------------
__global__ void points_k(const float* __restrict__ v2d, const float* __restrict__ v3d,
                         const int*   __restrict__ parents, const float* __restrict__ bary,
                         float* __restrict__ out_vw, float* __restrict__ out_c3) {
    const int idx = blockIdx.x * blockDim.x + threadIdx.x;
    if (idx >= NPT) return;
    const int b = idx / NPTS;
    const int n = idx - b * NPTS;
    const int kk = n % KB;

    const float w0 = __ldg(&bary[kk * 3 + 0]);
    const float w1 = __ldg(&bary[kk * 3 + 1]);
    const float w2 = __ldg(&bary[kk * 3 + 2]);

    const int p0 = __ldg(&parents[n * 3 + 0]);
    const int p1 = __ldg(&parents[n * 3 + 1]);
    const int p2 = __ldg(&parents[n * 3 + 2]);

    const float* v2b = v2d + (size_t)b * NV * 2;
    const float* v3b = v3d + (size_t)b * NV * 3;

    const float2 a2 = *reinterpret_cast<const float2*>(v2b + 2 * p0);
    const float2 b2 = *reinterpret_cast<const float2*>(v2b + 2 * p1);
    const float2 c2 = *reinterpret_cast<const float2*>(v2b + 2 * p2);
    const float cx = w0 * a2.x + w1 * b2.x + w2 * c2.x;
    const float cy = w0 * a2.y + w1 * b2.y + w2 * c2.y;

    const float ax = v3b[3 * p0], ay = v3b[3 * p0 + 1], az = v3b[3 * p0 + 2];
    const float bx = v3b[3 * p1], by = v3b[3 * p1 + 1], bz = v3b[3 * p1 + 2];
    const float gx = v3b[3 * p2], gy = v3b[3 * p2 + 1], gz = v3b[3 * p2 + 2];

    const float c3x = w0 * ax + w1 * bx + w2 * gx;
    const float c3y = w0 * ay + w1 * by + w2 * gy;
    const float c3z = w0 * az + w1 * bz + w2 * gz;

    // face normal
    const float e1x = bx - ax, e1y = by - ay, e1z = bz - az;
    const float e2x = gx - ax, e2y = gy - ay, e2z = gz - az;
    float nx = e1y * e2z - e1z * e2y;
    float ny = e1z * e2x - e1x * e2z;
    float nz = e1x * e2y - e1y * e2x;
    const float nrm = sqrtf(nx * nx + ny * ny + nz * nz) + 1e-8f;
    nx /= nrm; ny /= nrm; nz /= nrm;

    const float cl = sqrtf(c3x * c3x + c3y * c3y + c3z * c3z) + 1e-8f;
    const float vx = -c3x / cl, vy = -c3y / cl, vz = -c3z / cl;
    const float ang = fmaxf(nx * vx + ny * vy + nz * vz, 0.0f);

    // depth-based visibility
    const int xcd = min(max((int)rintf(cx), 0), IMW - 1);
    const int ycd = min(max((int)rintf(cy), 0), IMH - 1);
    const float dsamp = g_depth[b * HWIMG + ycd * IMW + xcd];
    const bool vis = (c3z <= dsamp + 1e-3f) || isinf(dsamp);

    out_vw[idx] = vis ? ang : 0.0f;
    out_c3[(size_t)idx * 3 + 0] = c3x;
    out_c3[(size_t)idx * 3 + 1] = c3y;
    out_c3[(size_t)idx * 3 + 2] = c3z;

    // grid-sample pixel coords (same formula chain as reference)
    const float gxn = cx / (float)(IMW - 1) * 2.0f - 1.0f;
    const float gyn = cy / (float)(IMH - 1) * 2.0f - 1.0f;
    const float px = (gxn + 1.0f) * 0.5f * (float)(WF - 1);
    const float py = (gyn + 1.0f) * 0.5f * (float)(HF - 1);

    // bilinear params
    const float x0f = floorf(px), y0f = floorf(py);
    const float wx = px - x0f, wy = py - y0f;
    const int x0 = (int)x0f, y0 = (int)y0f;

    const bool ix0 = (x0 >= 0) && (x0 < WF);
    const bool ix1 = (x0 + 1 >= 0) && (x0 + 1 < WF);
    const bool iy0 = (y0 >= 0) && (y0 < HF);
    const bool iy1 = (y0 + 1 >= 0) && (y0 + 1 < HF);

    const float w00 = (1.0f - wx) * (1.0f - wy) * (float)(ix0 && iy0);
    const float w10 = wx * (1.0f - wy)          * (float)(ix1 && iy0);
    const float w01 = (1.0f - wx) * wy          * (float)(ix0 && iy1);
    const float w11 = wx * wy                   * (float)(ix1 && iy1);

    const int xc0 = min(max(x0, 0), WF - 1);
    const int xc1 = min(max(x0 + 1, 0), WF - 1);
    const int yc0 = min(max(y0, 0), HF - 1);
    const int yc1 = min(max(y0 + 1, 0), HF - 1);

    const int bin = b * HWF + yc0 * WF + xc0;     // pixel bin (also offset base)
    g_off[idx] = make_int4(bin * C8,
                           (b * HWF + yc0 * WF + xc1) * C8,
                           (b * HWF + yc1 * WF + xc0) * C8,
                           (b * HWF + yc1 * WF + xc1) * C8);
    g_wt[idx] = make_float4(w00, w10, w01, w11);
    atomicAdd(&g_hist[bin], 1);
}

// ---------------------------------------------------------------------------
// Kernel 4a: block-local exclusive scan. 64 blocks x 1024 threads, 1 bin each.
// Coalesced loads, 10-step shared scan. Writes block totals to g_bsum.
// ---------------------------------------------------------------------------
__global__ void __launch_bounds__(1024) prefix1_k() {
    __shared__ int ssum[1024];
    const int t = threadIdx.x;
    const int bin = blockIdx.x * 1024 + t;
    const int v = g_hist[bin];
    ssum[t] = v;
    __syncthreads();
#pragma unroll
    for (int off = 1; off < 1024; off <<= 1) {
        const int a = ssum[t];
        const int u = (t >= off) ? ssum[t - off] : 0;
        __syncthreads();
        ssum[t] = a + u;
        __syncthreads();
    }
    g_cursor[bin] = ssum[t] - v;            // exclusive within block
    if (t == 1023) g_bsum[blockIdx.x] = ssum[t];
}

// ---------------------------------------------------------------------------
// Kernel 4b: exclusive scan of the 64 block totals (in place). 1 tiny block.
// ---------------------------------------------------------------------------
__global__ void prefix2_k() {
    __shared__ int s[NSBLK];
    const int t = threadIdx.x;
    s[t] = g_bsum[t];
    __syncthreads();
#pragma unroll
    for (int off = 1; off < NSBLK; off <<= 1) {
        const int a = s[t];
        const int u = (t >= off) ? s[t - off] : 0;
        __syncthreads();
        s[t] = a + u;
        __syncthreads();
    }
    g_bsum[t] = (t == 0) ? 0 : s[t - 1];    // exclusive
}

// ---------------------------------------------------------------------------
// Kernel 5: permute params into pixel-sorted order (counting-sort scatter).
// Global slot = block offset (g_bsum) + block-local cursor. Slot order within
// a bin is nondeterministic but output is index-addressed, so results match.
// ---------------------------------------------------------------------------
__global__ void perm_k() {
    const int idx = blockIdx.x * blockDim.x + threadIdx.x;
    if (idx >= NPT) return;
    const int4 o = g_off[idx];
    const int bin = o.x >> 4;               // /C8 recovers b*HWF + y0*WF + x0
    const int slot = atomicAdd(&g_cursor[bin], 1) + g_bsum[bin >> 10];
    g_soff[slot] = o;
    g_swt[slot]  = g_wt[idx];
    g_ord[slot]  = idx;
}

// ---------------------------------------------------------------------------
// Kernel 6: bilinear sampling in pixel-sorted order. 16 lanes / point.
// Warp's 2 points almost always share a pixel -> corner loads broadcast and
// stay L1-hot across warps; param reads fully sequential. Output scattered by
// original index in 512B blocks (full sectors), streaming stores.
// ---------------------------------------------------------------------------
__global__ void __launch_bounds__(256) sample_k(float* __restrict__ out_feats) {
    const unsigned t  = blockIdx.x * blockDim.x + threadIdx.x;
    const unsigned gw = t >> 4;                 // sorted slot (16 lanes per point)
    if (gw >= (unsigned)NPT) return;
    const int lane = t & 15;

    const int4   o   = g_soff[gw];
    const float4 w   = g_swt[gw];
    const int    idx = g_ord[gw];

    const uint4 f00 = __ldg(&g_fmTh[o.x + lane]);
    const uint4 f10 = __ldg(&g_fmTh[o.y + lane]);
    const uint4 f01 = __ldg(&g_fmTh[o.z + lane]);
    const uint4 f11 = __ldg(&g_fmTh[o.w + lane]);

    const __half2 w00 = __float2half2_rn(w.x);
    const __half2 w10 = __float2half2_rn(w.y);
    const __half2 w01 = __float2half2_rn(w.z);
    const __half2 w11 = __float2half2_rn(w.w);

    const __half2* h00 = reinterpret_cast<const __half2*>(&f00);
    const __half2* h10 = reinterpret_cast<const __half2*>(&f10);
    const __half2* h01 = reinterpret_cast<const __half2*>(&f01);
    const __half2* h11 = reinterpret_cast<const __half2*>(&f11);

    float2 r[4];
#pragma unroll
    for (int k = 0; k < 4; k++) {
        __half2 acc = __hmul2(h00[k], w00);
        acc = __hfma2(h10[k], w10, acc);
        acc = __hfma2(h01[k], w01, acc);
        acc = __hfma2(h11[k], w11, acc);
        r[k] = __half22float2(acc);
    }

    float4* outp = reinterpret_cast<float4*>(out_feats) + (size_t)idx * (CCH / 4) + lane * 2;
    __stcs(outp,     make_float4(r[0].x, r[0].y, r[1].x, r[1].y));
    __stcs(outp + 1, make_float4(r[2].x, r[2].y, r[3].x, r[3].y));
}

// ---------------------------------------------------------------------------
extern "C" void kernel_launch(void* const* d_in, const int* in_sizes, int n_in,
                              void* d_out, int out_size) {
    const float* fm      = (const float*)d_in[0];
    const float* v2d     = (const float*)d_in[1];
    const float* v3d     = (const float*)d_in[2];
    const int*   parents = (const int*)  d_in[3];
    const float* bary    = (const float*)d_in[4];
    (void)in_sizes; (void)n_in; (void)out_size;

    float* out       = (float*)d_out;
    float* out_feats = out;                                    // (B,N,C)
    float* out_vw    = out + (size_t)BNUM * NPTS * CCH;        // (B,N)
    float* out_c3    = out_vw + (size_t)BNUM * NPTS;           // (B,N,3)

    transpose_k<<<dim3(HWF / 32, CCH / 32, BNUM), dim3(32, 8)>>>(fm);  // + inits
    scatter_k<<<(BNUM * NV + 255) / 256, 256>>>(v2d, v3d);
    points_k<<<(NPT + 255) / 256, 256>>>(v2d, v3d, parents, bary, out_vw, out_c3);
    prefix1_k<<<NSBLK, 1024>>>();
    prefix2_k<<<1, NSBLK>>>();
    perm_k<<<(NPT + 255) / 256, 256>>>();
    sample_k<<<((size_t)NPT * 16 + 255) / 256, 256>>>(out_feats);
}

// round 8
// speedup vs baseline: 1.8258x; 1.1458x over previous
#include <cuda_runtime.h>
#include <cuda_fp16.h>
#include <math_constants.h>
#include <cstdint>

// Problem dimensions (deterministic from setup_inputs)
#define BNUM 4
#define CCH 128          // channels
#define HF 128           // feature map height
#define WF 128           // feature map width
#define NV 10475         // vertices
#define NPTS 200000      // gaussians
#define KB 20            // bary rows
#define IMH 512
#define IMW 512
#define HWIMG (IMH*IMW)
#define HWF (HF*WF)
#define C8 (CCH / 8)     // uint4 (8 halves) per pixel = 16

// Scratch (static device globals -- no allocation allowed)
__device__ uint4  g_fmTh[(size_t)BNUM * HWF * C8];  // 16 MB fp16 transposed map (B,Hf,Wf,C)
__device__ float  g_depth[BNUM * HWIMG];            // 4 MB depth maps
__device__ float2 g_pxpy[BNUM * NPTS];              // 6.4 MB sampling coords

// ---------------------------------------------------------------------------
// Kernel A1 (aux): init depth maps to +inf (float4 stores)
// ---------------------------------------------------------------------------
__global__ void init_depth_k() {
    const int i = blockIdx.x * blockDim.x + threadIdx.x;
    if (i < BNUM * HWIMG / 4) {
        reinterpret_cast<float4*>(g_depth)[i] =
            make_float4(CUDART_INF_F, CUDART_INF_F, CUDART_INF_F, CUDART_INF_F);
    }
}

// ---------------------------------------------------------------------------
// Kernel A2 (aux): scatter-min vertex depths. z > 0 so int-cmp == float-cmp.
// ---------------------------------------------------------------------------
__global__ void scatter_k(const float* __restrict__ v2d, const float* __restrict__ v3d) {
    const int i = blockIdx.x * blockDim.x + threadIdx.x;
    if (i >= BNUM * NV) return;
    const float xf = rintf(v2d[2 * i]);       // round-half-even, matches jnp.round
    const float yf = rintf(v2d[2 * i + 1]);
    const int xi = (int)xf, yi = (int)yf;
    if (xi < 0 || xi >= IMW || yi < 0 || yi >= IMH) return;
    const int b = i / NV;
    const float z = v3d[3 * i + 2];
    atomicMin(reinterpret_cast<int*>(&g_depth[b * HWIMG + yi * IMW + xi]),
              __float_as_int(z));
}

// ---------------------------------------------------------------------------
// Kernel A3 (aux, 4 per-batch chunks): per-point geometry (R2 form, 27.5us
// measured for all 4 batches). Emits vw, c3, and pxpy for the sampler.
// ---------------------------------------------------------------------------
__global__ void __launch_bounds__(256) points_k(
        const int bsel,
        const float* __restrict__ v2d, const float* __restrict__ v3d,
        const int*   __restrict__ parents, const float* __restrict__ bary,
        float* __restrict__ out_vw, float* __restrict__ out_c3) {
    const int n = blockIdx.x * blockDim.x + threadIdx.x;
    if (n >= NPTS) return;
    const int b = bsel;
    const int idx = b * NPTS + n;
    const int kk = n % KB;

    const float w0 = __ldg(&bary[kk * 3 + 0]);
    const float w1 = __ldg(&bary[kk * 3 + 1]);
    const float w2 = __ldg(&bary[kk * 3 + 2]);

    const int p0 = __ldg(&parents[n * 3 + 0]);
    const int p1 = __ldg(&parents[n * 3 + 1]);
    const int p2 = __ldg(&parents[n * 3 + 2]);

    const float* v2b = v2d + (size_t)b * NV * 2;
    const float* v3b = v3d + (size_t)b * NV * 3;

    const float2 a2 = *reinterpret_cast<const float2*>(v2b + 2 * p0);
    const float2 b2 = *reinterpret_cast<const float2*>(v2b + 2 * p1);
    const float2 c2 = *reinterpret_cast<const float2*>(v2b + 2 * p2);
    const float cx = w0 * a2.x + w1 * b2.x + w2 * c2.x;
    const float cy = w0 * a2.y + w1 * b2.y + w2 * c2.y;

    const float ax = v3b[3 * p0], ay = v3b[3 * p0 + 1], az = v3b[3 * p0 + 2];
    const float bx = v3b[3 * p1], by = v3b[3 * p1 + 1], bz = v3b[3 * p1 + 2];
    const float gx = v3b[3 * p2], gy = v3b[3 * p2 + 1], gz = v3b[3 * p2 + 2];

    const float c3x = w0 * ax + w1 * bx + w2 * gx;
    const float c3y = w0 * ay + w1 * by + w2 * gy;
    const float c3z = w0 * az + w1 * bz + w2 * gz;

    // face normal
    const float e1x = bx - ax, e1y = by - ay, e1z = bz - az;
    const float e2x = gx - ax, e2y = gy - ay, e2z = gz - az;
    float nx = e1y * e2z - e1z * e2y;
    float ny = e1z * e2x - e1x * e2z;
    float nz = e1x * e2y - e1y * e2x;
    const float nrm = sqrtf(nx * nx + ny * ny + nz * nz) + 1e-8f;
    nx /= nrm; ny /= nrm; nz /= nrm;

    const float cl = sqrtf(c3x * c3x + c3y * c3y + c3z * c3z) + 1e-8f;
    const float vx = -c3x / cl, vy = -c3y / cl, vz = -c3z / cl;
    const float ang = fmaxf(nx * vx + ny * vy + nz * vz, 0.0f);

    // depth-based visibility
    const int xc = min(max((int)rintf(cx), 0), IMW - 1);
    const int yc = min(max((int)rintf(cy), 0), IMH - 1);
    const float dsamp = g_depth[b * HWIMG + yc * IMW + xc];
    const bool vis = (c3z <= dsamp + 1e-3f) || isinf(dsamp);

    out_vw[idx] = vis ? ang : 0.0f;
    out_c3[(size_t)idx * 3 + 0] = c3x;
    out_c3[(size_t)idx * 3 + 1] = c3y;
    out_c3[(size_t)idx * 3 + 2] = c3z;

    // grid-sample pixel coords (same formula chain as reference)
    const float gxn = cx / (float)(IMW - 1) * 2.0f - 1.0f;
    const float gyn = cy / (float)(IMH - 1) * 2.0f - 1.0f;
    const float px = (gxn + 1.0f) * 0.5f * (float)(WF - 1);
    const float py = (gyn + 1.0f) * 0.5f * (float)(HF - 1);
    g_pxpy[idx] = make_float2(px, py);
}

// ---------------------------------------------------------------------------
// Kernel M1 (main): transpose + fp16-convert feature map -> (B,Hf,Wf,C)
// ---------------------------------------------------------------------------
__global__ void transpose_k(const float* __restrict__ fm) {
    __shared__ float tile[32][33];
    const int b  = blockIdx.z;
    const int p0 = blockIdx.x * 32;   // pixel base (Hf*Wf dim)
    const int c0 = blockIdx.y * 32;   // channel base
    const float* src = fm + (size_t)b * CCH * HWF;
    __half2* dst = reinterpret_cast<__half2*>(g_fmTh) + (size_t)b * HWF * (CCH / 2);

    const int tid = threadIdx.y * 32 + threadIdx.x;
    {
        const int x = p0 + threadIdx.x;
        for (int j = threadIdx.y; j < 32; j += 8)
            tile[j][threadIdx.x] = src[(size_t)(c0 + j) * HWF + x];
    }
    __syncthreads();
    for (int e = tid; e < 32 * 16; e += 256) {
        const int pix = e >> 4;
        const int ch2 = e & 15;
        __half2 h = __floats2half2_rn(tile[2 * ch2][pix], tile[2 * ch2 + 1][pix]);
        dst[(size_t)(p0 + pix) * (CCH / 2) + (c0 / 2) + ch2] = h;
    }
}

// ---------------------------------------------------------------------------
// Kernel M2 (main, 4 per-batch chunks): bilinear sampling (R2/R3 shape,
// measured 118.0us for all batches; rel_err 2.08e-4). 16 lanes / point,
// f32 accumulate, streaming stores. Write-stream bound.
// ---------------------------------------------------------------------------
__device__ __forceinline__ void acc8(const uint4 v, const float w, float* acc) {
    const __half2* h = reinterpret_cast<const __half2*>(&v);
#pragma unroll
    for (int k = 0; k < 4; k++) {
        const float2 f = __half22float2(h[k]);
        acc[2 * k]     = fmaf(w, f.x, acc[2 * k]);
        acc[2 * k + 1] = fmaf(w, f.y, acc[2 * k + 1]);
    }
}

__global__ void __launch_bounds__(256) sample_k(const int bsel, float* __restrict__ out_feats) {
    const unsigned t  = blockIdx.x * blockDim.x + threadIdx.x;
    const unsigned gl = t >> 4;                 // local point id within batch
    if (gl >= (unsigned)NPTS) return;
    const int lane = t & 15;
    const unsigned gw = (unsigned)bsel * NPTS + gl;

    const float2 p = g_pxpy[gw];
    const float x0f = floorf(p.x), y0f = floorf(p.y);
    const float wx = p.x - x0f, wy = p.y - y0f;
    const int x0 = (int)x0f, y0 = (int)y0f;

    const bool ix0 = (x0 >= 0) && (x0 < WF);
    const bool ix1 = (x0 + 1 >= 0) && (x0 + 1 < WF);
    const bool iy0 = (y0 >= 0) && (y0 < HF);
    const bool iy1 = (y0 + 1 >= 0) && (y0 + 1 < HF);

    const float w00 = (1.0f - wx) * (1.0f - wy) * (float)(ix0 && iy0);
    const float w10 = wx * (1.0f - wy)          * (float)(ix1 && iy0);
    const float w01 = (1.0f - wx) * wy          * (float)(ix0 && iy1);
    const float w11 = wx * wy                   * (float)(ix1 && iy1);

    const int xc0 = min(max(x0, 0), WF - 1);
    const int xc1 = min(max(x0 + 1, 0), WF - 1);
    const int yc0 = min(max(y0, 0), HF - 1);
    const int yc1 = min(max(y0 + 1, 0), HF - 1);

    const uint4* base = g_fmTh + (size_t)bsel * HWF * C8;
    const uint4 f00 = __ldg(base + (size_t)(yc0 * WF + xc0) * C8 + lane);
    const uint4 f10 = __ldg(base + (size_t)(yc0 * WF + xc1) * C8 + lane);
    const uint4 f01 = __ldg(base + (size_t)(yc1 * WF + xc0) * C8 + lane);
    const uint4 f11 = __ldg(base + (size_t)(yc1 * WF + xc1) * C8 + lane);

    float acc[8] = {0.f, 0.f, 0.f, 0.f, 0.f, 0.f, 0.f, 0.f};
    acc8(f00, w00, acc);
    acc8(f10, w10, acc);
    acc8(f01, w01, acc);
    acc8(f11, w11, acc);

    float4* outp = reinterpret_cast<float4*>(out_feats) + (size_t)gw * (CCH / 4) + lane * 2;
    __stcs(outp,     make_float4(acc[0], acc[1], acc[2], acc[3]));
    __stcs(outp + 1, make_float4(acc[4], acc[5], acc[6], acc[7]));
}

// ---------------------------------------------------------------------------
// Launch: fork-join overlap. Aux stream: init -> scatter -> points (4 batch
// chunks, event after each). Main stream: transpose, then per-batch sample
// gated on the matching points event. points_b1..3 hide under sample_b0's
// DRAM write stream. Streams/events are host objects created once (no device
// memory allocation); identical GPU work is enqueued on every call.
// ---------------------------------------------------------------------------
extern "C" void kernel_launch(void* const* d_in, const int* in_sizes, int n_in,
                              void* d_out, int out_size) {
    const float* fm      = (const float*)d_in[0];
    const float* v2d     = (const float*)d_in[1];
    const float* v3d     = (const float*)d_in[2];
    const int*   parents = (const int*)  d_in[3];
    const float* bary    = (const float*)d_in[4];
    (void)in_sizes; (void)n_in; (void)out_size;

    float* out       = (float*)d_out;
    float* out_feats = out;                                    // (B,N,C)
    float* out_vw    = out + (size_t)BNUM * NPTS * CCH;        // (B,N)
    float* out_c3    = out_vw + (size_t)BNUM * NPTS;           // (B,N,3)

    static cudaStream_t aux = nullptr;
    static cudaEvent_t  ev_root = nullptr;
    static cudaEvent_t  ev_p[BNUM];
    if (aux == nullptr) {
        cudaStreamCreateWithFlags(&aux, cudaStreamNonBlocking);
        cudaEventCreateWithFlags(&ev_root, cudaEventDisableTiming);
        for (int b = 0; b < BNUM; b++)
            cudaEventCreateWithFlags(&ev_p[b], cudaEventDisableTiming);
    }

    // fork: aux branch ordered after everything already on the main stream
    cudaEventRecord(ev_root, 0);
    cudaStreamWaitEvent(aux, ev_root, 0);

    // aux branch: depth init -> scatter -> per-batch geometry
    init_depth_k<<<(BNUM * HWIMG / 4 + 255) / 256, 256, 0, aux>>>();
    scatter_k<<<(BNUM * NV + 255) / 256, 256, 0, aux>>>(v2d, v3d);
    for (int b = 0; b < BNUM; b++) {
        points_k<<<(NPTS + 255) / 256, 256, 0, aux>>>(b, v2d, v3d, parents, bary,
                                                      out_vw, out_c3);
        cudaEventRecord(ev_p[b], aux);
    }

    // main branch: feature-map transpose runs concurrently with aux
    transpose_k<<<dim3(HWF / 32, CCH / 32, BNUM), dim3(32, 8)>>>(fm);

    // join per batch: sample_b waits only on points_b (and transpose, by
    // stream order). sample_b0's 30us write stream hides points_b1..3.
    for (int b = 0; b < BNUM; b++) {
        cudaStreamWaitEvent(0, ev_p[b], 0);
        sample_k<<<((size_t)NPTS * 16 + 255) / 256, 256>>>(b, out_feats);
    }
}

// round 9
// speedup vs baseline: 1.8878x; 1.0339x over previous
#include <cuda_runtime.h>
#include <cuda_fp16.h>
#include <math_constants.h>
#include <cstdint>

// Problem dimensions (deterministic from setup_inputs)
#define BNUM 4
#define CCH 128          // channels
#define HF 128           // feature map height
#define WF 128           // feature map width
#define NV 10475         // vertices
#define NPTS 200000      // gaussians
#define KB 20            // bary rows
#define IMH 512
#define IMW 512
#define HWIMG (IMH*IMW)
#define HWF (HF*WF)
#define C8 (CCH / 8)     // uint4 (8 halves) per pixel = 16

// Scratch (static device globals -- no allocation allowed)
__device__ uint4  g_fmTh[(size_t)BNUM * HWF * C8];  // 16 MB fp16 transposed map (B,Hf,Wf,C)
__device__ float  g_depth[BNUM * HWIMG];            // 4 MB depth maps
__device__ float2 g_pxpy[BNUM * NPTS];              // 6.4 MB sampling coords
__device__ float4 g_v3p[BNUM * NV];                 // 670 KB float4-padded vertices3d

// ---------------------------------------------------------------------------
// Kernel A1 (aux): init depth maps to +inf AND pad v3d (stride-3) to float4
// so points_k gathers one LDG.128 per vertex instead of 3 strided LDG.32.
// ---------------------------------------------------------------------------
__global__ void init_pad_k(const float* __restrict__ v3d) {
    const int i = blockIdx.x * blockDim.x + threadIdx.x;
    if (i < BNUM * HWIMG / 4) {
        reinterpret_cast<float4*>(g_depth)[i] =
            make_float4(CUDART_INF_F, CUDART_INF_F, CUDART_INF_F, CUDART_INF_F);
    }
    if (i < BNUM * NV) {
        g_v3p[i] = make_float4(v3d[3 * i], v3d[3 * i + 1], v3d[3 * i + 2], 0.0f);
    }
}

// ---------------------------------------------------------------------------
// Kernel A2 (aux): scatter-min vertex depths. z > 0 so int-cmp == float-cmp.
// ---------------------------------------------------------------------------
__global__ void scatter_k(const float* __restrict__ v2d, const float* __restrict__ v3d) {
    const int i = blockIdx.x * blockDim.x + threadIdx.x;
    if (i >= BNUM * NV) return;
    const float xf = rintf(v2d[2 * i]);       // round-half-even, matches jnp.round
    const float yf = rintf(v2d[2 * i + 1]);
    const int xi = (int)xf, yi = (int)yf;
    if (xi < 0 || xi >= IMW || yi < 0 || yi >= IMH) return;
    const int b = i / NV;
    const float z = v3d[3 * i + 2];
    atomicMin(reinterpret_cast<int*>(&g_depth[b * HWIMG + yi * IMW + xi]),
              __float_as_int(z));
}

// ---------------------------------------------------------------------------
// Kernel A3 (aux): per-point geometry, fused over all (b,n) -- the measured
// 27.5us form -- with float4 vertex gathers (6 loads/thread instead of 12).
// ---------------------------------------------------------------------------
__global__ void points_k(const float* __restrict__ v2d,
                         const int*   __restrict__ parents, const float* __restrict__ bary,
                         float* __restrict__ out_vw, float* __restrict__ out_c3) {
    const int idx = blockIdx.x * blockDim.x + threadIdx.x;
    if (idx >= BNUM * NPTS) return;
    const int b = idx / NPTS;
    const int n = idx - b * NPTS;
    const int kk = n % KB;

    const float w0 = __ldg(&bary[kk * 3 + 0]);
    const float w1 = __ldg(&bary[kk * 3 + 1]);
    const float w2 = __ldg(&bary[kk * 3 + 2]);

    const int p0 = __ldg(&parents[n * 3 + 0]);
    const int p1 = __ldg(&parents[n * 3 + 1]);
    const int p2 = __ldg(&parents[n * 3 + 2]);

    const float*  v2b = v2d + (size_t)b * NV * 2;
    const float4* v3b = g_v3p + b * NV;

    const float2 a2 = *reinterpret_cast<const float2*>(v2b + 2 * p0);
    const float2 b2 = *reinterpret_cast<const float2*>(v2b + 2 * p1);
    const float2 c2 = *reinterpret_cast<const float2*>(v2b + 2 * p2);
    const float cx = w0 * a2.x + w1 * b2.x + w2 * c2.x;
    const float cy = w0 * a2.y + w1 * b2.y + w2 * c2.y;

    const float4 va = __ldg(&v3b[p0]);
    const float4 vb = __ldg(&v3b[p1]);
    const float4 vg = __ldg(&v3b[p2]);

    const float c3x = w0 * va.x + w1 * vb.x + w2 * vg.x;
    const float c3y = w0 * va.y + w1 * vb.y + w2 * vg.y;
    const float c3z = w0 * va.z + w1 * vb.z + w2 * vg.z;

    // face normal
    const float e1x = vb.x - va.x, e1y = vb.y - va.y, e1z = vb.z - va.z;
    const float e2x = vg.x - va.x, e2y = vg.y - va.y, e2z = vg.z - va.z;
    float nx = e1y * e2z - e1z * e2y;
    float ny = e1z * e2x - e1x * e2z;
    float nz = e1x * e2y - e1y * e2x;
    const float nrm = sqrtf(nx * nx + ny * ny + nz * nz) + 1e-8f;
    nx /= nrm; ny /= nrm; nz /= nrm;

    const float cl = sqrtf(c3x * c3x + c3y * c3y + c3z * c3z) + 1e-8f;
    const float vx = -c3x / cl, vy = -c3y / cl, vz = -c3z / cl;
    const float ang = fmaxf(nx * vx + ny * vy + nz * vz, 0.0f);

    // depth-based visibility
    const int xc = min(max((int)rintf(cx), 0), IMW - 1);
    const int yc = min(max((int)rintf(cy), 0), IMH - 1);
    const float dsamp = g_depth[b * HWIMG + yc * IMW + xc];
    const bool vis = (c3z <= dsamp + 1e-3f) || isinf(dsamp);

    out_vw[idx] = vis ? ang : 0.0f;
    out_c3[(size_t)idx * 3 + 0] = c3x;
    out_c3[(size_t)idx * 3 + 1] = c3y;
    out_c3[(size_t)idx * 3 + 2] = c3z;

    // grid-sample pixel coords (same formula chain as reference)
    const float gxn = cx / (float)(IMW - 1) * 2.0f - 1.0f;
    const float gyn = cy / (float)(IMH - 1) * 2.0f - 1.0f;
    const float px = (gxn + 1.0f) * 0.5f * (float)(WF - 1);
    const float py = (gyn + 1.0f) * 0.5f * (float)(HF - 1);
    g_pxpy[idx] = make_float2(px, py);
}

// ---------------------------------------------------------------------------
// Kernel M1 (main): transpose + fp16-convert feature map -> (B,Hf,Wf,C)
// ---------------------------------------------------------------------------
__global__ void transpose_k(const float* __restrict__ fm) {
    __shared__ float tile[32][33];
    const int b  = blockIdx.z;
    const int p0 = blockIdx.x * 32;   // pixel base (Hf*Wf dim)
    const int c0 = blockIdx.y * 32;   // channel base
    const float* src = fm + (size_t)b * CCH * HWF;
    __half2* dst = reinterpret_cast<__half2*>(g_fmTh) + (size_t)b * HWF * (CCH / 2);

    const int tid = threadIdx.y * 32 + threadIdx.x;
    {
        const int x = p0 + threadIdx.x;
        for (int j = threadIdx.y; j < 32; j += 8)
            tile[j][threadIdx.x] = src[(size_t)(c0 + j) * HWF + x];
    }
    __syncthreads();
    for (int e = tid; e < 32 * 16; e += 256) {
        const int pix = e >> 4;
        const int ch2 = e & 15;
        __half2 h = __floats2half2_rn(tile[2 * ch2][pix], tile[2 * ch2 + 1][pix]);
        dst[(size_t)(p0 + pix) * (CCH / 2) + (c0 / 2) + ch2] = h;
    }
}

// ---------------------------------------------------------------------------
// Kernel M2 (main): bilinear sampling -- exact R3 form, measured 118.0us,
// rel_err 2.08e-4. 16 lanes / point, f32 accumulate, streaming stores.
// Pinned at the HBM write-stream ceiling; do not touch.
// ---------------------------------------------------------------------------
__device__ __forceinline__ void acc8(const uint4 v, const float w, float* acc) {
    const __half2* h = reinterpret_cast<const __half2*>(&v);
#pragma unroll
    for (int k = 0; k < 4; k++) {
        const float2 f = __half22float2(h[k]);
        acc[2 * k]     = fmaf(w, f.x, acc[2 * k]);
        acc[2 * k + 1] = fmaf(w, f.y, acc[2 * k + 1]);
    }
}

__global__ void __launch_bounds__(256) sample_k(float* __restrict__ out_feats) {
    const unsigned t  = blockIdx.x * blockDim.x + threadIdx.x;
    const unsigned gw = t >> 4;                 // point id (16 lanes per point)
    if (gw >= (unsigned)(BNUM * NPTS)) return;
    const int lane = t & 15;
    const int b = gw / NPTS;

    const float2 p = g_pxpy[gw];
    const float x0f = floorf(p.x), y0f = floorf(p.y);
    const float wx = p.x - x0f, wy = p.y - y0f;
    const int x0 = (int)x0f, y0 = (int)y0f;

    const bool ix0 = (x0 >= 0) && (x0 < WF);
    const bool ix1 = (x0 + 1 >= 0) && (x0 + 1 < WF);
    const bool iy0 = (y0 >= 0) && (y0 < HF);
    const bool iy1 = (y0 + 1 >= 0) && (y0 + 1 < HF);

    const float w00 = (1.0f - wx) * (1.0f - wy) * (float)(ix0 && iy0);
    const float w10 = wx * (1.0f - wy)          * (float)(ix1 && iy0);
    const float w01 = (1.0f - wx) * wy          * (float)(ix0 && iy1);
    const float w11 = wx * wy                   * (float)(ix1 && iy1);

    const int xc0 = min(max(x0, 0), WF - 1);
    const int xc1 = min(max(x0 + 1, 0), WF - 1);
    const int yc0 = min(max(y0, 0), HF - 1);
    const int yc1 = min(max(y0 + 1, 0), HF - 1);

    const uint4* base = g_fmTh + (size_t)b * HWF * C8;
    const uint4 f00 = __ldg(base + (size_t)(yc0 * WF + xc0) * C8 + lane);
    const uint4 f10 = __ldg(base + (size_t)(yc0 * WF + xc1) * C8 + lane);
    const uint4 f01 = __ldg(base + (size_t)(yc1 * WF + xc0) * C8 + lane);
    const uint4 f11 = __ldg(base + (size_t)(yc1 * WF + xc1) * C8 + lane);

    float acc[8] = {0.f, 0.f, 0.f, 0.f, 0.f, 0.f, 0.f, 0.f};
    acc8(f00, w00, acc);
    acc8(f10, w10, acc);
    acc8(f01, w01, acc);
    acc8(f11, w11, acc);

    float4* outp = reinterpret_cast<float4*>(out_feats) + (size_t)gw * (CCH / 4) + lane * 2;
    __stcs(outp,     make_float4(acc[0], acc[1], acc[2], acc[3]));
    __stcs(outp + 1, make_float4(acc[4], acc[5], acc[6], acc[7]));
}

// ---------------------------------------------------------------------------
// Launch: fork-join. Aux: init/pad -> scatter -> points (fused, one event).
// Main: transpose (overlaps aux), wait event, one full sample launch.
// Streams/events are host objects created once; identical GPU work every call.
// ---------------------------------------------------------------------------
extern "C" void kernel_launch(void* const* d_in, const int* in_sizes, int n_in,
                              void* d_out, int out_size) {
    const float* fm      = (const float*)d_in[0];
    const float* v2d     = (const float*)d_in[1];
    const float* v3d     = (const float*)d_in[2];
    const int*   parents = (const int*)  d_in[3];
    const float* bary    = (const float*)d_in[4];
    (void)in_sizes; (void)n_in; (void)out_size;

    float* out       = (float*)d_out;
    float* out_feats = out;                                    // (B,N,C)
    float* out_vw    = out + (size_t)BNUM * NPTS * CCH;        // (B,N)
    float* out_c3    = out_vw + (size_t)BNUM * NPTS;           // (B,N,3)

    static cudaStream_t aux = nullptr;
    static cudaEvent_t  ev_root = nullptr, ev_pts = nullptr;
    if (aux == nullptr) {
        cudaStreamCreateWithFlags(&aux, cudaStreamNonBlocking);
        cudaEventCreateWithFlags(&ev_root, cudaEventDisableTiming);
        cudaEventCreateWithFlags(&ev_pts,  cudaEventDisableTiming);
    }

    // fork
    cudaEventRecord(ev_root, 0);
    cudaStreamWaitEvent(aux, ev_root, 0);

    // aux branch: depth init + vertex pad -> scatter -> fused geometry
    init_pad_k<<<(BNUM * HWIMG / 4 + 255) / 256, 256, 0, aux>>>(v3d);
    scatter_k<<<(BNUM * NV + 255) / 256, 256, 0, aux>>>(v2d, v3d);
    points_k<<<(BNUM * NPTS + 255) / 256, 256, 0, aux>>>(v2d, parents, bary,
                                                         out_vw, out_c3);
    cudaEventRecord(ev_pts, aux);

    // main branch: transpose overlaps the aux chain
    transpose_k<<<dim3(HWF / 32, CCH / 32, BNUM), dim3(32, 8)>>>(fm);

    // join: sample needs both transpose (stream order) and points (event)
    cudaStreamWaitEvent(0, ev_pts, 0);
    sample_k<<<((size_t)BNUM * NPTS * 16 + 255) / 256, 256>>>(out_feats);
}

// round 10
// speedup vs baseline: 1.9890x; 1.0536x over previous
#include <cuda_runtime.h>
#include <cuda_fp16.h>
#include <math_constants.h>
#include <cstdint>

// Problem dimensions (deterministic from setup_inputs)
#define BNUM 4
#define CCH 128          // channels
#define HF 128           // feature map height
#define WF 128           // feature map width
#define NV 10475         // vertices
#define NPTS 200000      // gaussians
#define KB 20            // bary rows
#define IMH 512
#define IMW 512
#define HWIMG (IMH*IMW)
#define HWF (HF*WF)
#define C8 (CCH / 8)     // uint4 (8 halves) per pixel = 16

// Scratch (static device globals -- no allocation allowed)
__device__ uint4  g_fmTh[(size_t)BNUM * HWF * C8];  // 16 MB fp16 transposed map (B,Hf,Wf,C)
__device__ float  g_depth[BNUM * HWIMG];            // 4 MB depth maps
__device__ float2 g_pxpy[BNUM * NPTS];              // 6.4 MB sampling coords
__device__ float4 g_v3p[BNUM * NV];                 // 670 KB float4-padded vertices3d

// ---------------------------------------------------------------------------
// Kernel A1 (aux): init depth maps to +inf AND pad v3d (stride-3) to float4.
// ---------------------------------------------------------------------------
__global__ void init_pad_k(const float* __restrict__ v3d) {
    const int i = blockIdx.x * blockDim.x + threadIdx.x;
    if (i < BNUM * HWIMG / 4) {
        reinterpret_cast<float4*>(g_depth)[i] =
            make_float4(CUDART_INF_F, CUDART_INF_F, CUDART_INF_F, CUDART_INF_F);
    }
    if (i < BNUM * NV) {
        g_v3p[i] = make_float4(v3d[3 * i], v3d[3 * i + 1], v3d[3 * i + 2], 0.0f);
    }
}

// ---------------------------------------------------------------------------
// Kernel A2 (aux): scatter-min vertex depths. z > 0 so int-cmp == float-cmp.
// ---------------------------------------------------------------------------
__global__ void scatter_k(const float* __restrict__ v2d, const float* __restrict__ v3d) {
    const int i = blockIdx.x * blockDim.x + threadIdx.x;
    if (i >= BNUM * NV) return;
    const float xf = rintf(v2d[2 * i]);       // round-half-even, matches jnp.round
    const float yf = rintf(v2d[2 * i + 1]);
    const int xi = (int)xf, yi = (int)yf;
    if (xi < 0 || xi >= IMW || yi < 0 || yi >= IMH) return;
    const int b = i / NV;
    const float z = v3d[3 * i + 2];
    atomicMin(reinterpret_cast<int*>(&g_depth[b * HWIMG + yi * IMW + xi]),
              __float_as_int(z));
}

// ---------------------------------------------------------------------------
// Kernel A3 (aux): per-point geometry, fused over all (b,n), float4 gathers.
// ---------------------------------------------------------------------------
__global__ void points_k(const float* __restrict__ v2d,
                         const int*   __restrict__ parents, const float* __restrict__ bary,
                         float* __restrict__ out_vw, float* __restrict__ out_c3) {
    const int idx = blockIdx.x * blockDim.x + threadIdx.x;
    if (idx >= BNUM * NPTS) return;
    const int b = idx / NPTS;
    const int n = idx - b * NPTS;
    const int kk = n % KB;

    const float w0 = __ldg(&bary[kk * 3 + 0]);
    const float w1 = __ldg(&bary[kk * 3 + 1]);
    const float w2 = __ldg(&bary[kk * 3 + 2]);

    const int p0 = __ldg(&parents[n * 3 + 0]);
    const int p1 = __ldg(&parents[n * 3 + 1]);
    const int p2 = __ldg(&parents[n * 3 + 2]);

    const float*  v2b = v2d + (size_t)b * NV * 2;
    const float4* v3b = g_v3p + b * NV;

    const float2 a2 = *reinterpret_cast<const float2*>(v2b + 2 * p0);
    const float2 b2 = *reinterpret_cast<const float2*>(v2b + 2 * p1);
    const float2 c2 = *reinterpret_cast<const float2*>(v2b + 2 * p2);
    const float cx = w0 * a2.x + w1 * b2.x + w2 * c2.x;
    const float cy = w0 * a2.y + w1 * b2.y + w2 * c2.y;

    const float4 va = __ldg(&v3b[p0]);
    const float4 vb = __ldg(&v3b[p1]);
    const float4 vg = __ldg(&v3b[p2]);

    const float c3x = w0 * va.x + w1 * vb.x + w2 * vg.x;
    const float c3y = w0 * va.y + w1 * vb.y + w2 * vg.y;
    const float c3z = w0 * va.z + w1 * vb.z + w2 * vg.z;

    // face normal
    const float e1x = vb.x - va.x, e1y = vb.y - va.y, e1z = vb.z - va.z;
    const float e2x = vg.x - va.x, e2y = vg.y - va.y, e2z = vg.z - va.z;
    float nx = e1y * e2z - e1z * e2y;
    float ny = e1z * e2x - e1x * e2z;
    float nz = e1x * e2y - e1y * e2x;
    const float nrm = sqrtf(nx * nx + ny * ny + nz * nz) + 1e-8f;
    nx /= nrm; ny /= nrm; nz /= nrm;

    const float cl = sqrtf(c3x * c3x + c3y * c3y + c3z * c3z) + 1e-8f;
    const float vx = -c3x / cl, vy = -c3y / cl, vz = -c3z / cl;
    const float ang = fmaxf(nx * vx + ny * vy + nz * vz, 0.0f);

    // depth-based visibility
    const int xc = min(max((int)rintf(cx), 0), IMW - 1);
    const int yc = min(max((int)rintf(cy), 0), IMH - 1);
    const float dsamp = g_depth[b * HWIMG + yc * IMW + xc];
    const bool vis = (c3z <= dsamp + 1e-3f) || isinf(dsamp);

    out_vw[idx] = vis ? ang : 0.0f;
    out_c3[(size_t)idx * 3 + 0] = c3x;
    out_c3[(size_t)idx * 3 + 1] = c3y;
    out_c3[(size_t)idx * 3 + 2] = c3z;

    // grid-sample pixel coords (same formula chain as reference)
    const float gxn = cx / (float)(IMW - 1) * 2.0f - 1.0f;
    const float gyn = cy / (float)(IMH - 1) * 2.0f - 1.0f;
    const float px = (gxn + 1.0f) * 0.5f * (float)(WF - 1);
    const float py = (gyn + 1.0f) * 0.5f * (float)(HF - 1);
    g_pxpy[idx] = make_float2(px, py);
}

// ---------------------------------------------------------------------------
// Kernel M1 (main): vectorized transpose + fp16 convert.
// Block handles 32 channels x 128 pixels. float4 loads (LDG.128), STS.128
// into padded tile (conflict-free), uint4 fp16 stores. ~4x fewer load insts
// than the 32x32 scalar version (which measured 21.4us contended).
// ---------------------------------------------------------------------------
__global__ void __launch_bounds__(256) transpose_k(const float* __restrict__ fm) {
    __shared__ float4 tile4[32][33];
    const int b  = blockIdx.z;
    const int p0 = blockIdx.x * 128;  // pixel base
    const int c0 = blockIdx.y * 32;   // channel base
    const float4* src4 = reinterpret_cast<const float4*>(fm + (size_t)b * CCH * HWF);
    uint4* dst = g_fmTh + (size_t)b * HWF * C8;

    const int tx = threadIdx.x;       // 0..31 (pixel quad)
    const int ty = threadIdx.y;       // 0..7
    const int tid = ty * 32 + tx;

#pragma unroll
    for (int k = 0; k < 4; k++) {
        const int r = ty + 8 * k;     // channel row 0..31
        tile4[r][tx] = src4[(size_t)(c0 + r) * (HWF / 4) + (p0 / 4) + tx];
    }
    __syncthreads();

    const float* tilef = reinterpret_cast<const float*>(tile4);  // row stride 132 floats
#pragma unroll
    for (int it = 0; it < 2; it++) {
        const int e = tid + it * 256;     // 0..511
        const int pix = e >> 2;           // 0..127
        const int q = e & 3;              // channel-octet within the 32
        uint4 o;
        uint32_t* ow = reinterpret_cast<uint32_t*>(&o);
#pragma unroll
        for (int h = 0; h < 4; h++) {
            const int c = q * 8 + h * 2;
            const __half2 hh = __floats2half2_rn(tilef[c * 132 + pix],
                                                 tilef[(c + 1) * 132 + pix]);
            ow[h] = *reinterpret_cast<const uint32_t*>(&hh);
        }
        dst[(size_t)(p0 + pix) * C8 + (c0 / 8) + q] = o;
    }
}

// ---------------------------------------------------------------------------
// Kernel M2 (main): bilinear sampling, R3 arithmetic (rel_err 2.08e-4),
// but PLAIN stores instead of __stcs. The two STG.128 per thread write
// interleaved half-lines; write-back L2 merges them into full 128B lines
// before eviction, removing the ~2x DRAM write amplification that evict-
// first streaming stores caused (the invariant behind 118us).
// ---------------------------------------------------------------------------
__device__ __forceinline__ void acc8(const uint4 v, const float w, float* acc) {
    const __half2* h = reinterpret_cast<const __half2*>(&v);
#pragma unroll
    for (int k = 0; k < 4; k++) {
        const float2 f = __half22float2(h[k]);
        acc[2 * k]     = fmaf(w, f.x, acc[2 * k]);
        acc[2 * k + 1] = fmaf(w, f.y, acc[2 * k + 1]);
    }
}

__global__ void __launch_bounds__(256) sample_k(float* __restrict__ out_feats) {
    const unsigned t  = blockIdx.x * blockDim.x + threadIdx.x;
    const unsigned gw = t >> 4;                 // point id (16 lanes per point)
    if (gw >= (unsigned)(BNUM * NPTS)) return;
    const int lane = t & 15;
    const int b = gw / NPTS;

    const float2 p = g_pxpy[gw];
    const float x0f = floorf(p.x), y0f = floorf(p.y);
    const float wx = p.x - x0f, wy = p.y - y0f;
    const int x0 = (int)x0f, y0 = (int)y0f;

    const bool ix0 = (x0 >= 0) && (x0 < WF);
    const bool ix1 = (x0 + 1 >= 0) && (x0 + 1 < WF);
    const bool iy0 = (y0 >= 0) && (y0 < HF);
    const bool iy1 = (y0 + 1 >= 0) && (y0 + 1 < HF);

    const float w00 = (1.0f - wx) * (1.0f - wy) * (float)(ix0 && iy0);
    const float w10 = wx * (1.0f - wy)          * (float)(ix1 && iy0);
    const float w01 = (1.0f - wx) * wy          * (float)(ix0 && iy1);
    const float w11 = wx * wy                   * (float)(ix1 && iy1);

    const int xc0 = min(max(x0, 0), WF - 1);
    const int xc1 = min(max(x0 + 1, 0), WF - 1);
    const int yc0 = min(max(y0, 0), HF - 1);
    const int yc1 = min(max(y0 + 1, 0), HF - 1);

    const uint4* base = g_fmTh + (size_t)b * HWF * C8;
    const uint4 f00 = __ldg(base + (size_t)(yc0 * WF + xc0) * C8 + lane);
    const uint4 f10 = __ldg(base + (size_t)(yc0 * WF + xc1) * C8 + lane);
    const uint4 f01 = __ldg(base + (size_t)(yc1 * WF + xc0) * C8 + lane);
    const uint4 f11 = __ldg(base + (size_t)(yc1 * WF + xc1) * C8 + lane);

    float acc[8] = {0.f, 0.f, 0.f, 0.f, 0.f, 0.f, 0.f, 0.f};
    acc8(f00, w00, acc);
    acc8(f10, w10, acc);
    acc8(f01, w01, acc);
    acc8(f11, w11, acc);

    float4* outp = reinterpret_cast<float4*>(out_feats) + (size_t)gw * (CCH / 4) + lane * 2;
    outp[0] = make_float4(acc[0], acc[1], acc[2], acc[3]);
    outp[1] = make_float4(acc[4], acc[5], acc[6], acc[7]);
}

// ---------------------------------------------------------------------------
// Launch: fork-join. Aux: init/pad -> scatter -> points (one event).
// Main: transpose (overlaps aux), wait event, one full sample launch.
// ---------------------------------------------------------------------------
extern "C" void kernel_launch(void* const* d_in, const int* in_sizes, int n_in,
                              void* d_out, int out_size) {
    const float* fm      = (const float*)d_in[0];
    const float* v2d     = (const float*)d_in[1];
    const float* v3d     = (const float*)d_in[2];
    const int*   parents = (const int*)  d_in[3];
    const float* bary    = (const float*)d_in[4];
    (void)in_sizes; (void)n_in; (void)out_size;

    float* out       = (float*)d_out;
    float* out_feats = out;                                    // (B,N,C)
    float* out_vw    = out + (size_t)BNUM * NPTS * CCH;        // (B,N)
    float* out_c3    = out_vw + (size_t)BNUM * NPTS;           // (B,N,3)

    static cudaStream_t aux = nullptr;
    static cudaEvent_t  ev_root = nullptr, ev_pts = nullptr;
    if (aux == nullptr) {
        cudaStreamCreateWithFlags(&aux, cudaStreamNonBlocking);
        cudaEventCreateWithFlags(&ev_root, cudaEventDisableTiming);
        cudaEventCreateWithFlags(&ev_pts,  cudaEventDisableTiming);
    }

    // fork
    cudaEventRecord(ev_root, 0);
    cudaStreamWaitEvent(aux, ev_root, 0);

    // aux branch: depth init + vertex pad -> scatter -> fused geometry
    init_pad_k<<<(BNUM * HWIMG / 4 + 255) / 256, 256, 0, aux>>>(v3d);
    scatter_k<<<(BNUM * NV + 255) / 256, 256, 0, aux>>>(v2d, v3d);
    points_k<<<(BNUM * NPTS + 255) / 256, 256, 0, aux>>>(v2d, parents, bary,
                                                         out_vw, out_c3);
    cudaEventRecord(ev_pts, aux);

    // main branch: transpose overlaps the aux chain
    transpose_k<<<dim3(HWF / 128, CCH / 32, BNUM), dim3(32, 8)>>>(fm);

    // join: sample needs both transpose (stream order) and points (event)
    cudaStreamWaitEvent(0, ev_pts, 0);
    sample_k<<<((size_t)BNUM * NPTS * 16 + 255) / 256, 256>>>(out_feats);
}

// round 12
// speedup vs baseline: 2.0358x; 1.0235x over previous
#include <cuda_runtime.h>
#include <cuda_fp16.h>
#include <math_constants.h>
#include <cstdint>

// Problem dimensions (deterministic from setup_inputs)
#define BNUM 4
#define CCH 128          // channels
#define HF 128           // feature map height
#define WF 128           // feature map width
#define NV 10475         // vertices
#define NPTS 200000      // gaussians
#define KB 20            // bary rows
#define IMH 512
#define IMW 512
#define HWIMG (IMH*IMW)
#define HWF (HF*WF)
#define C8 (CCH / 8)     // uint4 (8 halves) per pixel = 16
#define NPT (BNUM * NPTS)
#define NBINS (BNUM * HWF)   // 65536 top-left-pixel bins
#define NSBLK 64             // scan blocks (1024 bins each)

// Scratch (static device globals -- no allocation allowed)
__device__ uint4  g_fmTh[(size_t)BNUM * HWF * C8];  // 16 MB fp16 transposed map (B,Hf,Wf,C)
__device__ float  g_depth[BNUM * HWIMG];            // 4 MB depth maps
__device__ float4 g_v3p[BNUM * NV];                 // float4-padded vertices3d
__device__ uint4  g_wt4 [NPT];                      // packed half2x4 weights (orig order)
__device__ int    g_bin [NPT];                      // per-point bin id
__device__ uint4  g_swt [NPT];                      // sorted packed weights
__device__ int    g_ord [NPT];                      // sorted slot -> original point idx
__device__ int    g_hist[NBINS];                    // bin histogram
__device__ int    g_start[NBINS];                   // global exclusive bin starts
__device__ int    g_cursor[NBINS];                  // mutable cursors (perm) -> bin ends
__device__ int    g_bsum[NSBLK];                    // scan-block totals -> exclusive offsets

// ---------------------------------------------------------------------------
// Kernel A1 (aux): init depth (+inf), zero histogram, pad v3d to float4.
// ---------------------------------------------------------------------------
__global__ void init_pad_k(const float* __restrict__ v3d) {
    const int i = blockIdx.x * blockDim.x + threadIdx.x;
    if (i < BNUM * HWIMG / 4) {
        reinterpret_cast<float4*>(g_depth)[i] =
            make_float4(CUDART_INF_F, CUDART_INF_F, CUDART_INF_F, CUDART_INF_F);
    }
    if (i < NBINS / 4) {
        reinterpret_cast<int4*>(g_hist)[i] = make_int4(0, 0, 0, 0);
    }
    if (i < BNUM * NV) {
        g_v3p[i] = make_float4(v3d[3 * i], v3d[3 * i + 1], v3d[3 * i + 2], 0.0f);
    }
}

// ---------------------------------------------------------------------------
// Kernel A2 (aux): scatter-min vertex depths. z > 0 so int-cmp == float-cmp.
// ---------------------------------------------------------------------------
__global__ void scatter_k(const float* __restrict__ v2d, const float* __restrict__ v3d) {
    const int i = blockIdx.x * blockDim.x + threadIdx.x;
    if (i >= BNUM * NV) return;
    const float xf = rintf(v2d[2 * i]);       // round-half-even, matches jnp.round
    const float yf = rintf(v2d[2 * i + 1]);
    const int xi = (int)xf, yi = (int)yf;
    if (xi < 0 || xi >= IMW || yi < 0 || yi >= IMH) return;
    const int b = i / NV;
    const float z = v3d[3 * i + 2];
    atomicMin(reinterpret_cast<int*>(&g_depth[b * HWIMG + yi * IMW + xi]),
              __float_as_int(z));
}

// ---------------------------------------------------------------------------
// Kernel A3 (aux): per-point geometry + packed fp16 weights + bin histogram.
// EDGE FIX vs R11: for x0 < 0 the nonzero weights (w10,w11) actually sample
// the clamped column x=0 == the bin's corner00/corner01 -> shift them into
// the 00/01 slots. Symmetrically for y0 < 0. After the remap, every nonzero
// weight multiplies exactly the corner the bin decode produces.
// ---------------------------------------------------------------------------
__global__ void points_k(const float* __restrict__ v2d,
                         const int*   __restrict__ parents, const float* __restrict__ bary,
                         float* __restrict__ out_vw, float* __restrict__ out_c3) {
    const int idx = blockIdx.x * blockDim.x + threadIdx.x;
    if (idx >= NPT) return;
    const int b = idx / NPTS;
    const int n = idx - b * NPTS;
    const int kk = n % KB;

    const float w0 = __ldg(&bary[kk * 3 + 0]);
    const float w1 = __ldg(&bary[kk * 3 + 1]);
    const float w2 = __ldg(&bary[kk * 3 + 2]);

    const int p0 = __ldg(&parents[n * 3 + 0]);
    const int p1 = __ldg(&parents[n * 3 + 1]);
    const int p2 = __ldg(&parents[n * 3 + 2]);

    const float*  v2b = v2d + (size_t)b * NV * 2;
    const float4* v3b = g_v3p + b * NV;

    const float2 a2 = *reinterpret_cast<const float2*>(v2b + 2 * p0);
    const float2 b2 = *reinterpret_cast<const float2*>(v2b + 2 * p1);
    const float2 c2 = *reinterpret_cast<const float2*>(v2b + 2 * p2);
    const float cx = w0 * a2.x + w1 * b2.x + w2 * c2.x;
    const float cy = w0 * a2.y + w1 * b2.y + w2 * c2.y;

    const float4 va = __ldg(&v3b[p0]);
    const float4 vb = __ldg(&v3b[p1]);
    const float4 vg = __ldg(&v3b[p2]);

    const float c3x = w0 * va.x + w1 * vb.x + w2 * vg.x;
    const float c3y = w0 * va.y + w1 * vb.y + w2 * vg.y;
    const float c3z = w0 * va.z + w1 * vb.z + w2 * vg.z;

    // face normal
    const float e1x = vb.x - va.x, e1y = vb.y - va.y, e1z = vb.z - va.z;
    const float e2x = vg.x - va.x, e2y = vg.y - va.y, e2z = vg.z - va.z;
    float nx = e1y * e2z - e1z * e2y;
    float ny = e1z * e2x - e1x * e2z;
    float nz = e1x * e2y - e1y * e2x;
    const float nrm = sqrtf(nx * nx + ny * ny + nz * nz) + 1e-8f;
    nx /= nrm; ny /= nrm; nz /= nrm;

    const float cl = sqrtf(c3x * c3x + c3y * c3y + c3z * c3z) + 1e-8f;
    const float vx = -c3x / cl, vy = -c3y / cl, vz = -c3z / cl;
    const float ang = fmaxf(nx * vx + ny * vy + nz * vz, 0.0f);

    // depth-based visibility
    const int xcd = min(max((int)rintf(cx), 0), IMW - 1);
    const int ycd = min(max((int)rintf(cy), 0), IMH - 1);
    const float dsamp = g_depth[b * HWIMG + ycd * IMW + xcd];
    const bool vis = (c3z <= dsamp + 1e-3f) || isinf(dsamp);

    out_vw[idx] = vis ? ang : 0.0f;
    out_c3[(size_t)idx * 3 + 0] = c3x;
    out_c3[(size_t)idx * 3 + 1] = c3y;
    out_c3[(size_t)idx * 3 + 2] = c3z;

    // grid-sample pixel coords -> bilinear params
    const float gxn = cx / (float)(IMW - 1) * 2.0f - 1.0f;
    const float gyn = cy / (float)(IMH - 1) * 2.0f - 1.0f;
    const float px = (gxn + 1.0f) * 0.5f * (float)(WF - 1);
    const float py = (gyn + 1.0f) * 0.5f * (float)(HF - 1);

    const float x0f = floorf(px), y0f = floorf(py);
    const float wx = px - x0f, wy = py - y0f;
    const int x0 = (int)x0f, y0 = (int)y0f;

    const bool ix0 = (x0 >= 0) && (x0 < WF);
    const bool ix1 = (x0 + 1 >= 0) && (x0 + 1 < WF);
    const bool iy0 = (y0 >= 0) && (y0 < HF);
    const bool iy1 = (y0 + 1 >= 0) && (y0 + 1 < HF);

    float w00 = (1.0f - wx) * (1.0f - wy) * (float)(ix0 && iy0);
    float w10 = wx * (1.0f - wy)          * (float)(ix1 && iy0);
    float w01 = (1.0f - wx) * wy          * (float)(ix0 && iy1);
    float w11 = wx * wy                   * (float)(ix1 && iy1);

    // EDGE FIX: fold off-left / off-top contributions onto the clamped corner
    if (x0 < 0) { w00 = w10; w01 = w11; w10 = 0.0f; w11 = 0.0f; }
    if (y0 < 0) { w00 = w01; w10 = w11; w01 = 0.0f; w11 = 0.0f; }

    const int xc0 = min(max(x0, 0), WF - 1);
    const int yc0 = min(max(y0, 0), HF - 1);
    const int bin = b * HWF + yc0 * WF + xc0;   // == global pixel idx of corner00

    // pack weights as 4 duplicated half2 (one uint4 broadcast load in sampler)
    uint4 wp;
    const __half2 h0 = __float2half2_rn(w00);
    const __half2 h1 = __float2half2_rn(w10);
    const __half2 h2 = __float2half2_rn(w01);
    const __half2 h3 = __float2half2_rn(w11);
    wp.x = *reinterpret_cast<const uint32_t*>(&h0);
    wp.y = *reinterpret_cast<const uint32_t*>(&h1);
    wp.z = *reinterpret_cast<const uint32_t*>(&h2);
    wp.w = *reinterpret_cast<const uint32_t*>(&h3);
    g_wt4[idx] = wp;
    g_bin[idx] = bin;
    atomicAdd(&g_hist[bin], 1);
}

// ---------------------------------------------------------------------------
// Kernel A4a: block-local exclusive scan (64 blocks x 1024 bins).
// ---------------------------------------------------------------------------
__global__ void __launch_bounds__(1024) prefix1_k() {
    __shared__ int ssum[1024];
    const int t = threadIdx.x;
    const int bin = blockIdx.x * 1024 + t;
    const int v = g_hist[bin];
    ssum[t] = v;
    __syncthreads();
#pragma unroll
    for (int off = 1; off < 1024; off <<= 1) {
        const int a = ssum[t];
        const int u = (t >= off) ? ssum[t - off] : 0;
        __syncthreads();
        ssum[t] = a + u;
        __syncthreads();
    }
    g_start[bin] = ssum[t] - v;             // exclusive within block
    if (t == 1023) g_bsum[blockIdx.x] = ssum[t];
}

// ---------------------------------------------------------------------------
// Kernel A4b: exclusive scan of 64 block totals.
// ---------------------------------------------------------------------------
__global__ void prefix2_k() {
    __shared__ int s[NSBLK];
    const int t = threadIdx.x;
    s[t] = g_bsum[t];
    __syncthreads();
#pragma unroll
    for (int off = 1; off < NSBLK; off <<= 1) {
        const int a = s[t];
        const int u = (t >= off) ? s[t - off] : 0;
        __syncthreads();
        s[t] = a + u;
        __syncthreads();
    }
    g_bsum[t] = (t == 0) ? 0 : s[t - 1];    // exclusive
}

// ---------------------------------------------------------------------------
// Kernel A4c: globalize starts; init cursors.
// ---------------------------------------------------------------------------
__global__ void fix_k() {
    const int bin = blockIdx.x * blockDim.x + threadIdx.x;
    if (bin >= NBINS) return;
    const int v = g_start[bin] + g_bsum[bin >> 10];
    g_start[bin]  = v;
    g_cursor[bin] = v;
}

// ---------------------------------------------------------------------------
// Kernel A5: counting-sort scatter of (weights, orig idx) into bin order.
// Slot order within a bin is nondeterministic; output is index-addressed.
// ---------------------------------------------------------------------------
__global__ void perm_k() {
    const int idx = blockIdx.x * blockDim.x + threadIdx.x;
    if (idx >= NPT) return;
    const int bin = g_bin[idx];
    const int slot = atomicAdd(&g_cursor[bin], 1);
    g_swt[slot] = g_wt4[idx];
    g_ord[slot] = idx;
}

// ---------------------------------------------------------------------------
// Kernel M1 (main): vectorized transpose + fp16 convert (measured 13.3us).
// ---------------------------------------------------------------------------
__global__ void __launch_bounds__(256) transpose_k(const float* __restrict__ fm) {
    __shared__ float4 tile4[32][33];
    const int b  = blockIdx.z;
    const int p0 = blockIdx.x * 128;  // pixel base
    const int c0 = blockIdx.y * 32;   // channel base
    const float4* src4 = reinterpret_cast<const float4*>(fm + (size_t)b * CCH * HWF);
    uint4* dst = g_fmTh + (size_t)b * HWF * C8;

    const int tx = threadIdx.x;
    const int ty = threadIdx.y;
    const int tid = ty * 32 + tx;

#pragma unroll
    for (int k = 0; k < 4; k++) {
        const int r = ty + 8 * k;
        tile4[r][tx] = src4[(size_t)(c0 + r) * (HWF / 4) + (p0 / 4) + tx];
    }
    __syncthreads();

    const float* tilef = reinterpret_cast<const float*>(tile4);  // row stride 132
#pragma unroll
    for (int it = 0; it < 2; it++) {
        const int e = tid + it * 256;
        const int pix = e >> 2;
        const int q = e & 3;
        uint4 o;
        uint32_t* ow = reinterpret_cast<uint32_t*>(&o);
#pragma unroll
        for (int h = 0; h < 4; h++) {
            const int c = q * 8 + h * 2;
            const __half2 hh = __floats2half2_rn(tilef[c * 132 + pix],
                                                 tilef[(c + 1) * 132 + pix]);
            ow[h] = *reinterpret_cast<const uint32_t*>(&hh);
        }
        dst[(size_t)(p0 + pix) * C8 + (c0 / 8) + q] = o;
    }
}

// ---------------------------------------------------------------------------
// Kernel M2 (main): warp-per-bin gather sampling. The 4 corner vectors are
// loaded ONCE per bin into registers (lane owns 4 channels), then reused for
// every point in the bin: one broadcast weight load + 8 HFMA2 + one 512B
// coalesced STG per point. Per-point L1 read traffic ~20B instead of 1KB.
// ---------------------------------------------------------------------------
__global__ void __launch_bounds__(256) sample_k(float* __restrict__ out_feats) {
    const int bin = blockIdx.x * 8 + (threadIdx.x >> 5);   // warp-per-bin
    if (bin >= NBINS) return;
    const int lane = threadIdx.x & 31;

    const int start = g_start[bin];
    const int end   = g_cursor[bin];     // == start + count after perm
    if (start >= end) return;

    // decode corner pixels: bin == global pixel index of corner00
    const int p  = bin & (HWF - 1);
    const int x0 = p & (WF - 1);
    const int y0 = p >> 7;
    const int dx = (x0 < WF - 1) ? 1 : 0;
    const int dy = (y0 < HF - 1) ? WF : 0;

    const uint2* fm2 = reinterpret_cast<const uint2*>(g_fmTh);
    const uint2 c00 = __ldg(fm2 + (size_t)(bin)           * 32 + lane);
    const uint2 c10 = __ldg(fm2 + (size_t)(bin + dx)      * 32 + lane);
    const uint2 c01 = __ldg(fm2 + (size_t)(bin + dy)      * 32 + lane);
    const uint2 c11 = __ldg(fm2 + (size_t)(bin + dx + dy) * 32 + lane);

    const __half2 a00 = *reinterpret_cast<const __half2*>(&c00.x);
    const __half2 b00 = *reinterpret_cast<const __half2*>(&c00.y);
    const __half2 a10 = *reinterpret_cast<const __half2*>(&c10.x);
    const __half2 b10 = *reinterpret_cast<const __half2*>(&c10.y);
    const __half2 a01 = *reinterpret_cast<const __half2*>(&c01.x);
    const __half2 b01 = *reinterpret_cast<const __half2*>(&c01.y);
    const __half2 a11 = *reinterpret_cast<const __half2*>(&c11.x);
    const __half2 b11 = *reinterpret_cast<const __half2*>(&c11.y);

    for (int s = start; s < end; s++) {
        const uint4 wp  = __ldg(&g_swt[s]);    // broadcast (all lanes same addr)
        const int  oidx = __ldg(&g_ord[s]);

        const __half2 W00 = *reinterpret_cast<const __half2*>(&wp.x);
        const __half2 W10 = *reinterpret_cast<const __half2*>(&wp.y);
        const __half2 W01 = *reinterpret_cast<const __half2*>(&wp.z);
        const __half2 W11 = *reinterpret_cast<const __half2*>(&wp.w);

        __half2 ra = __hmul2(a00, W00);
        ra = __hfma2(a10, W10, ra);
        ra = __hfma2(a01, W01, ra);
        ra = __hfma2(a11, W11, ra);
        __half2 rb = __hmul2(b00, W00);
        rb = __hfma2(b10, W10, rb);
        rb = __hfma2(b01, W01, rb);
        rb = __hfma2(b11, W11, rb);

        const float2 fa = __half22float2(ra);
        const float2 fb = __half22float2(rb);
        float4* outp = reinterpret_cast<float4*>(out_feats) + (size_t)oidx * (CCH / 4) + lane;
        *outp = make_float4(fa.x, fa.y, fb.x, fb.y);
    }
}

// ---------------------------------------------------------------------------
// Launch: aux: init/pad -> scatter -> points(+hist) -> scan -> fix -> perm.
// Main: transpose (overlaps aux), wait event, warp-per-bin sample.
// Streams/events are host objects created once; identical work every call.
// ---------------------------------------------------------------------------
extern "C" void kernel_launch(void* const* d_in, const int* in_sizes, int n_in,
                              void* d_out, int out_size) {
    const float* fm      = (const float*)d_in[0];
    const float* v2d     = (const float*)d_in[1];
    const float* v3d     = (const float*)d_in[2];
    const int*   parents = (const int*)  d_in[3];
    const float* bary    = (const float*)d_in[4];
    (void)in_sizes; (void)n_in; (void)out_size;

    float* out       = (float*)d_out;
    float* out_feats = out;                                    // (B,N,C)
    float* out_vw    = out + (size_t)BNUM * NPTS * CCH;        // (B,N)
    float* out_c3    = out_vw + (size_t)BNUM * NPTS;           // (B,N,3)

    static cudaStream_t aux = nullptr;
    static cudaEvent_t  ev_root = nullptr, ev_pts = nullptr;
    if (aux == nullptr) {
        cudaStreamCreateWithFlags(&aux, cudaStreamNonBlocking);
        cudaEventCreateWithFlags(&ev_root, cudaEventDisableTiming);
        cudaEventCreateWithFlags(&ev_pts,  cudaEventDisableTiming);
    }

    // fork
    cudaEventRecord(ev_root, 0);
    cudaStreamWaitEvent(aux, ev_root, 0);

    // aux branch
    init_pad_k<<<(BNUM * HWIMG / 4 + 255) / 256, 256, 0, aux>>>(v3d);
    scatter_k<<<(BNUM * NV + 255) / 256, 256, 0, aux>>>(v2d, v3d);
    points_k<<<(NPT + 255) / 256, 256, 0, aux>>>(v2d, parents, bary, out_vw, out_c3);
    prefix1_k<<<NSBLK, 1024, 0, aux>>>();
    prefix2_k<<<1, NSBLK, 0, aux>>>();
    fix_k<<<NBINS / 256, 256, 0, aux>>>();
    perm_k<<<(NPT + 255) / 256, 256, 0, aux>>>();
    cudaEventRecord(ev_pts, aux);

    // main branch: transpose overlaps the aux chain
    transpose_k<<<dim3(HWF / 128, CCH / 32, BNUM), dim3(32, 8)>>>(fm);

    // join: sample needs transpose (stream order) and the sorted params (event)
    cudaStreamWaitEvent(0, ev_pts, 0);
    sample_k<<<NBINS / 8, 256>>>(out_feats);
}

// round 14
// speedup vs baseline: 2.0803x; 1.0219x over previous
#include <cuda_runtime.h>
#include <cuda_fp16.h>
#include <math_constants.h>
#include <cstdint>

// Problem dimensions (deterministic from setup_inputs)
#define BNUM 4
#define CCH 128          // channels
#define HF 128           // feature map height
#define WF 128           // feature map width
#define NV 10475         // vertices
#define NPTS 200000      // gaussians
#define KB 20            // bary rows
#define IMH 512
#define IMW 512
#define HWIMG (IMH*IMW)
#define HWF (HF*WF)
#define C8 (CCH / 8)     // uint4 (8 halves) per pixel = 16
#define NPT (BNUM * NPTS)
#define NBINS (BNUM * HWF)   // 65536 top-left-pixel bins
#define NSBLK 64             // scan blocks (1024 bins each)

// Scratch (static device globals -- no allocation allowed)
__device__ uint4  g_fmTh[(size_t)BNUM * HWF * C8];  // 16 MB fp16 transposed map (B,Hf,Wf,C)
__device__ float  g_depth[BNUM * HWIMG];            // 4 MB depth maps
__device__ float4 g_v3p[BNUM * NV];                 // float4-padded vertices3d
__device__ float2 g_ctr[NPT];                       // centers2d (coords -> geom)
__device__ uint4  g_wt4 [NPT];                      // packed half2x4 weights (orig order)
__device__ int    g_bin [NPT];                      // per-point bin id
__device__ uint4  g_swt [NPT];                      // sorted packed weights
__device__ int    g_ord [NPT];                      // sorted slot -> original point idx
__device__ int    g_hist[NBINS];                    // bin histogram
__device__ int    g_start[NBINS];                   // global exclusive bin starts
__device__ int    g_cursor[NBINS];                  // mutable cursors (perm) -> bin ends
__device__ int    g_bsum[NSBLK];                    // scan-block totals -> exclusive offsets

// ---------------------------------------------------------------------------
// Kernel 1 (main): init depth (+inf), zero histogram, pad v3d to float4.
// ---------------------------------------------------------------------------
__global__ void init_pad_k(const float* __restrict__ v3d) {
    const int i = blockIdx.x * blockDim.x + threadIdx.x;
    if (i < BNUM * HWIMG / 4) {
        reinterpret_cast<float4*>(g_depth)[i] =
            make_float4(CUDART_INF_F, CUDART_INF_F, CUDART_INF_F, CUDART_INF_F);
    }
    if (i < NBINS / 4) {
        reinterpret_cast<int4*>(g_hist)[i] = make_int4(0, 0, 0, 0);
    }
    if (i < BNUM * NV) {
        g_v3p[i] = make_float4(v3d[3 * i], v3d[3 * i + 1], v3d[3 * i + 2], 0.0f);
    }
}

// ---------------------------------------------------------------------------
// Kernel 2 (main, CRITICAL PATH): centers2d -> bilinear weights + bin + hist.
// Only the v2d gathers -- no 3D geometry. Stores centers for geom_k.
// Edge fold (proven in R12): off-left/off-top weight mass moves onto the
// clamped corner so every nonzero weight matches the bin-decoded corner.
// ---------------------------------------------------------------------------
__global__ void coords_k(const float* __restrict__ v2d,
                         const int*   __restrict__ parents,
                         const float* __restrict__ bary) {
    const int idx = blockIdx.x * blockDim.x + threadIdx.x;
    if (idx >= NPT) return;
    const int b = idx / NPTS;
    const int n = idx - b * NPTS;
    const int kk = n % KB;

    const float w0 = __ldg(&bary[kk * 3 + 0]);
    const float w1 = __ldg(&bary[kk * 3 + 1]);
    const float w2 = __ldg(&bary[kk * 3 + 2]);

    const int p0 = __ldg(&parents[n * 3 + 0]);
    const int p1 = __ldg(&parents[n * 3 + 1]);
    const int p2 = __ldg(&parents[n * 3 + 2]);

    const float* v2b = v2d + (size_t)b * NV * 2;
    const float2 a2 = *reinterpret_cast<const float2*>(v2b + 2 * p0);
    const float2 b2 = *reinterpret_cast<const float2*>(v2b + 2 * p1);
    const float2 c2 = *reinterpret_cast<const float2*>(v2b + 2 * p2);
    const float cx = w0 * a2.x + w1 * b2.x + w2 * c2.x;
    const float cy = w0 * a2.y + w1 * b2.y + w2 * c2.y;

    g_ctr[idx] = make_float2(cx, cy);

    // grid-sample pixel coords -> bilinear params (reference formula chain)
    const float gxn = cx / (float)(IMW - 1) * 2.0f - 1.0f;
    const float gyn = cy / (float)(IMH - 1) * 2.0f - 1.0f;
    const float px = (gxn + 1.0f) * 0.5f * (float)(WF - 1);
    const float py = (gyn + 1.0f) * 0.5f * (float)(HF - 1);

    const float x0f = floorf(px), y0f = floorf(py);
    const float wx = px - x0f, wy = py - y0f;
    const int x0 = (int)x0f, y0 = (int)y0f;

    const bool ix0 = (x0 >= 0) && (x0 < WF);
    const bool ix1 = (x0 + 1 >= 0) && (x0 + 1 < WF);
    const bool iy0 = (y0 >= 0) && (y0 < HF);
    const bool iy1 = (y0 + 1 >= 0) && (y0 + 1 < HF);

    float w00 = (1.0f - wx) * (1.0f - wy) * (float)(ix0 && iy0);
    float w10 = wx * (1.0f - wy)          * (float)(ix1 && iy0);
    float w01 = (1.0f - wx) * wy          * (float)(ix0 && iy1);
    float w11 = wx * wy                   * (float)(ix1 && iy1);

    if (x0 < 0) { w00 = w10; w01 = w11; w10 = 0.0f; w11 = 0.0f; }
    if (y0 < 0) { w00 = w01; w10 = w11; w01 = 0.0f; w11 = 0.0f; }

    const int xc0 = min(max(x0, 0), WF - 1);
    const int yc0 = min(max(y0, 0), HF - 1);
    const int bin = b * HWF + yc0 * WF + xc0;

    uint4 wp;
    const __half2 h0 = __float2half2_rn(w00);
    const __half2 h1 = __float2half2_rn(w10);
    const __half2 h2 = __float2half2_rn(w01);
    const __half2 h3 = __float2half2_rn(w11);
    wp.x = *reinterpret_cast<const uint32_t*>(&h0);
    wp.y = *reinterpret_cast<const uint32_t*>(&h1);
    wp.z = *reinterpret_cast<const uint32_t*>(&h2);
    wp.w = *reinterpret_cast<const uint32_t*>(&h3);
    g_wt4[idx] = wp;
    g_bin[idx] = bin;
    atomicAdd(&g_hist[bin], 1);
}

// ---------------------------------------------------------------------------
// Kernel A2 (aux): scatter-min vertex depths. z > 0 so int-cmp == float-cmp.
// ---------------------------------------------------------------------------
__global__ void scatter_k(const float* __restrict__ v2d, const float* __restrict__ v3d) {
    const int i = blockIdx.x * blockDim.x + threadIdx.x;
    if (i >= BNUM * NV) return;
    const float xf = rintf(v2d[2 * i]);       // round-half-even, matches jnp.round
    const float yf = rintf(v2d[2 * i + 1]);
    const int xi = (int)xf, yi = (int)yf;
    if (xi < 0 || xi >= IMW || yi < 0 || yi >= IMH) return;
    const int b = i / NV;
    const float z = v3d[3 * i + 2];
    atomicMin(reinterpret_cast<int*>(&g_depth[b * HWIMG + yi * IMW + xi]),
              __float_as_int(z));
}

// ---------------------------------------------------------------------------
// Kernel A3 (aux, OFF critical path -- overlaps scan/perm/sample):
// 3D geometry: centers3d, normals, angle weight, visibility.
// ---------------------------------------------------------------------------
__global__ void geom_k(const int* __restrict__ parents, const float* __restrict__ bary,
                       float* __restrict__ out_vw, float* __restrict__ out_c3) {
    const int idx = blockIdx.x * blockDim.x + threadIdx.x;
    if (idx >= NPT) return;
    const int b = idx / NPTS;
    const int n = idx - b * NPTS;
    const int kk = n % KB;

    const float w0 = __ldg(&bary[kk * 3 + 0]);
    const float w1 = __ldg(&bary[kk * 3 + 1]);
    const float w2 = __ldg(&bary[kk * 3 + 2]);

    const int p0 = __ldg(&parents[n * 3 + 0]);
    const int p1 = __ldg(&parents[n * 3 + 1]);
    const int p2 = __ldg(&parents[n * 3 + 2]);

    const float4* v3b = g_v3p + b * NV;
    const float4 va = __ldg(&v3b[p0]);
    const float4 vb = __ldg(&v3b[p1]);
    const float4 vg = __ldg(&v3b[p2]);

    const float c3x = w0 * va.x + w1 * vb.x + w2 * vg.x;
    const float c3y = w0 * va.y + w1 * vb.y + w2 * vg.y;
    const float c3z = w0 * va.z + w1 * vb.z + w2 * vg.z;

    const float e1x = vb.x - va.x, e1y = vb.y - va.y, e1z = vb.z - va.z;
    const float e2x = vg.x - va.x, e2y = vg.y - va.y, e2z = vg.z - va.z;
    float nx = e1y * e2z - e1z * e2y;
    float ny = e1z * e2x - e1x * e2z;
    float nz = e1x * e2y - e1y * e2x;
    const float nrm = sqrtf(nx * nx + ny * ny + nz * nz) + 1e-8f;
    nx /= nrm; ny /= nrm; nz /= nrm;

    const float cl = sqrtf(c3x * c3x + c3y * c3y + c3z * c3z) + 1e-8f;
    const float vx = -c3x / cl, vy = -c3y / cl, vz = -c3z / cl;
    const float ang = fmaxf(nx * vx + ny * vy + nz * vz, 0.0f);

    const float2 c = g_ctr[idx];
    const int xc = min(max((int)rintf(c.x), 0), IMW - 1);
    const int yc = min(max((int)rintf(c.y), 0), IMH - 1);
    const float dsamp = g_depth[b * HWIMG + yc * IMW + xc];
    const bool vis = (c3z <= dsamp + 1e-3f) || isinf(dsamp);

    out_vw[idx] = vis ? ang : 0.0f;
    out_c3[(size_t)idx * 3 + 0] = c3x;
    out_c3[(size_t)idx * 3 + 1] = c3y;
    out_c3[(size_t)idx * 3 + 2] = c3z;
}

// ---------------------------------------------------------------------------
// Scan kernels (measured ~7us total).
// ---------------------------------------------------------------------------
__global__ void __launch_bounds__(1024) prefix1_k() {
    __shared__ int ssum[1024];
    const int t = threadIdx.x;
    const int bin = blockIdx.x * 1024 + t;
    const int v = g_hist[bin];
    ssum[t] = v;
    __syncthreads();
#pragma unroll
    for (int off = 1; off < 1024; off <<= 1) {
        const int a = ssum[t];
        const int u = (t >= off) ? ssum[t - off] : 0;
        __syncthreads();
        ssum[t] = a + u;
        __syncthreads();
    }
    g_start[bin] = ssum[t] - v;
    if (t == 1023) g_bsum[blockIdx.x] = ssum[t];
}

__global__ void prefix2_k() {
    __shared__ int s[NSBLK];
    const int t = threadIdx.x;
    s[t] = g_bsum[t];
    __syncthreads();
#pragma unroll
    for (int off = 1; off < NSBLK; off <<= 1) {
        const int a = s[t];
        const int u = (t >= off) ? s[t - off] : 0;
        __syncthreads();
        s[t] = a + u;
        __syncthreads();
    }
    g_bsum[t] = (t == 0) ? 0 : s[t - 1];
}

__global__ void fix_k() {
    const int bin = blockIdx.x * blockDim.x + threadIdx.x;
    if (bin >= NBINS) return;
    const int v = g_start[bin] + g_bsum[bin >> 10];
    g_start[bin]  = v;
    g_cursor[bin] = v;
}

// ---------------------------------------------------------------------------
// Kernel 5 (main): counting-sort scatter into bin order.
// ---------------------------------------------------------------------------
__global__ void perm_k() {
    const int idx = blockIdx.x * blockDim.x + threadIdx.x;
    if (idx >= NPT) return;
    const int bin = g_bin[idx];
    const int slot = atomicAdd(&g_cursor[bin], 1);
    g_swt[slot] = g_wt4[idx];
    g_ord[slot] = idx;
}

// ---------------------------------------------------------------------------
// Kernel A1 (aux): vectorized transpose + fp16 convert (measured 13.3us).
// ---------------------------------------------------------------------------
__global__ void __launch_bounds__(256) transpose_k(const float* __restrict__ fm) {
    __shared__ float4 tile4[32][33];
    const int b  = blockIdx.z;
    const int p0 = blockIdx.x * 128;
    const int c0 = blockIdx.y * 32;
    const float4* src4 = reinterpret_cast<const float4*>(fm + (size_t)b * CCH * HWF);
    uint4* dst = g_fmTh + (size_t)b * HWF * C8;

    const int tx = threadIdx.x;
    const int ty = threadIdx.y;
    const int tid = ty * 32 + tx;

#pragma unroll
    for (int k = 0; k < 4; k++) {
        const int r = ty + 8 * k;
        tile4[r][tx] = src4[(size_t)(c0 + r) * (HWF / 4) + (p0 / 4) + tx];
    }
    __syncthreads();

    const float* tilef = reinterpret_cast<const float*>(tile4);  // row stride 132
#pragma unroll
    for (int it = 0; it < 2; it++) {
        const int e = tid + it * 256;
        const int pix = e >> 2;
        const int q = e & 3;
        uint4 o;
        uint32_t* ow = reinterpret_cast<uint32_t*>(&o);
#pragma unroll
        for (int h = 0; h < 4; h++) {
            const int c = q * 8 + h * 2;
            const __half2 hh = __floats2half2_rn(tilef[c * 132 + pix],
                                                 tilef[(c + 1) * 132 + pix]);
            ow[h] = *reinterpret_cast<const uint32_t*>(&hh);
        }
        dst[(size_t)(p0 + pix) * C8 + (c0 / 8) + q] = o;
    }
}

// ---------------------------------------------------------------------------
// Kernel 6 (main): warp-per-bin gather sampling (R12, ~97us, write-bound).
// ---------------------------------------------------------------------------
__global__ void __launch_bounds__(256) sample_k(float* __restrict__ out_feats) {
    const int bin = blockIdx.x * 8 + (threadIdx.x >> 5);
    if (bin >= NBINS) return;
    const int lane = threadIdx.x & 31;

    const int start = g_start[bin];
    const int end   = g_cursor[bin];
    if (start >= end) return;

    const int p  = bin & (HWF - 1);
    const int x0 = p & (WF - 1);
    const int y0 = p >> 7;
    const int dx = (x0 < WF - 1) ? 1 : 0;
    const int dy = (y0 < HF - 1) ? WF : 0;

    const uint2* fm2 = reinterpret_cast<const uint2*>(g_fmTh);
    const uint2 c00 = __ldg(fm2 + (size_t)(bin)           * 32 + lane);
    const uint2 c10 = __ldg(fm2 + (size_t)(bin + dx)      * 32 + lane);
    const uint2 c01 = __ldg(fm2 + (size_t)(bin + dy)      * 32 + lane);
    const uint2 c11 = __ldg(fm2 + (size_t)(bin + dx + dy) * 32 + lane);

    const __half2 a00 = *reinterpret_cast<const __half2*>(&c00.x);
    const __half2 b00 = *reinterpret_cast<const __half2*>(&c00.y);
    const __half2 a10 = *reinterpret_cast<const __half2*>(&c10.x);
    const __half2 b10 = *reinterpret_cast<const __half2*>(&c10.y);
    const __half2 a01 = *reinterpret_cast<const __half2*>(&c01.x);
    const __half2 b01 = *reinterpret_cast<const __half2*>(&c01.y);
    const __half2 a11 = *reinterpret_cast<const __half2*>(&c11.x);
    const __half2 b11 = *reinterpret_cast<const __half2*>(&c11.y);

    for (int s = start; s < end; s++) {
        const uint4 wp  = __ldg(&g_swt[s]);
        const int  oidx = __ldg(&g_ord[s]);

        const __half2 W00 = *reinterpret_cast<const __half2*>(&wp.x);
        const __half2 W10 = *reinterpret_cast<const __half2*>(&wp.y);
        const __half2 W01 = *reinterpret_cast<const __half2*>(&wp.z);
        const __half2 W11 = *reinterpret_cast<const __half2*>(&wp.w);

        __half2 ra = __hmul2(a00, W00);
        ra = __hfma2(a10, W10, ra);
        ra = __hfma2(a01, W01, ra);
        ra = __hfma2(a11, W11, ra);
        __half2 rb = __hmul2(b00, W00);
        rb = __hfma2(b10, W10, rb);
        rb = __hfma2(b01, W01, rb);
        rb = __hfma2(b11, W11, rb);

        const float2 fa = __half22float2(ra);
        const float2 fb = __half22float2(rb);
        float4* outp = reinterpret_cast<float4*>(out_feats) + (size_t)oidx * (CCH / 4) + lane;
        *outp = make_float4(fa.x, fa.y, fb.x, fb.y);
    }
}

// ---------------------------------------------------------------------------
// Launch graph (all forked work joins back to stream 0 before return):
//   main: init -> coords -> prefix1 -> prefix2 -> fix -> perm
//         -> (wait ev_t) sample -> (wait ev_geom)  [join]
//   aux:  transpose (ev_t) -> (wait ev_init) scatter
//         -> (wait ev_crd) geom (ev_geom)
// geom overlaps scan/perm/sample; transpose overlaps init/coords.
// ---------------------------------------------------------------------------
extern "C" void kernel_launch(void* const* d_in, const int* in_sizes, int n_in,
                              void* d_out, int out_size) {
    const float* fm      = (const float*)d_in[0];
    const float* v2d     = (const float*)d_in[1];
    const float* v3d     = (const float*)d_in[2];
    const int*   parents = (const int*)  d_in[3];
    const float* bary    = (const float*)d_in[4];
    (void)in_sizes; (void)n_in; (void)out_size;

    float* out       = (float*)d_out;
    float* out_feats = out;                                    // (B,N,C)
    float* out_vw    = out + (size_t)BNUM * NPTS * CCH;        // (B,N)
    float* out_c3    = out_vw + (size_t)BNUM * NPTS;           // (B,N,3)

    static cudaStream_t aux = nullptr;
    static cudaEvent_t  ev_root = nullptr, ev_init = nullptr, ev_crd = nullptr,
                        ev_t = nullptr, ev_geom = nullptr;
    if (aux == nullptr) {
        cudaStreamCreateWithFlags(&aux, cudaStreamNonBlocking);
        cudaEventCreateWithFlags(&ev_root, cudaEventDisableTiming);
        cudaEventCreateWithFlags(&ev_init, cudaEventDisableTiming);
        cudaEventCreateWithFlags(&ev_crd,  cudaEventDisableTiming);
        cudaEventCreateWithFlags(&ev_t,    cudaEventDisableTiming);
        cudaEventCreateWithFlags(&ev_geom, cudaEventDisableTiming);
    }

    // fork
    cudaEventRecord(ev_root, 0);
    cudaStreamWaitEvent(aux, ev_root, 0);

    // aux: transpose immediately (depends only on fm)
    transpose_k<<<dim3(HWF / 128, CCH / 32, BNUM), dim3(32, 8), 0, aux>>>(fm);
    cudaEventRecord(ev_t, aux);

    // main critical path: init -> coords -> scan -> perm
    init_pad_k<<<(BNUM * HWIMG / 4 + 255) / 256, 256>>>(v3d);
    cudaEventRecord(ev_init, 0);
    coords_k<<<(NPT + 255) / 256, 256>>>(v2d, parents, bary);
    cudaEventRecord(ev_crd, 0);
    prefix1_k<<<NSBLK, 1024>>>();
    prefix2_k<<<1, NSBLK>>>();
    fix_k<<<NBINS / 256, 256>>>();
    perm_k<<<(NPT + 255) / 256, 256>>>();

    // aux: depth scatter (needs init), then geometry (needs coords' centers)
    cudaStreamWaitEvent(aux, ev_init, 0);
    scatter_k<<<(BNUM * NV + 255) / 256, 256, 0, aux>>>(v2d, v3d);
    cudaStreamWaitEvent(aux, ev_crd, 0);
    geom_k<<<(NPT + 255) / 256, 256, 0, aux>>>(parents, bary, out_vw, out_c3);
    cudaEventRecord(ev_geom, aux);

    // main: sample needs transpose + sorted params
    cudaStreamWaitEvent(0, ev_t, 0);
    sample_k<<<NBINS / 8, 256>>>(out_feats);

    // join the aux branch back into stream 0 (required for graph capture;
    // free at runtime since geom finishes long before sample does)
    cudaStreamWaitEvent(0, ev_geom, 0);
}

// round 15
// speedup vs baseline: 2.1099x; 1.0142x over previous
#include <cuda_runtime.h>
#include <cuda_fp16.h>
#include <math_constants.h>
#include <cstdint>

// Problem dimensions (deterministic from setup_inputs)
#define BNUM 4
#define CCH 128          // channels
#define HF 128           // feature map height
#define WF 128           // feature map width
#define NV 10475         // vertices
#define NPTS 200000      // gaussians
#define KB 20            // bary rows
#define IMH 512
#define IMW 512
#define HWIMG (IMH*IMW)
#define HWF (HF*WF)
#define C8 (CCH / 8)     // uint4 (8 halves) per pixel = 16
#define NPT (BNUM * NPTS)
#define NBINS (BNUM * HWF)   // 65536 top-left-pixel bins
#define NSBLK 64             // scan blocks (1024 bins each)

// Scratch (static device globals -- no allocation allowed)
__device__ uint4  g_fmTh[(size_t)BNUM * HWF * C8];  // 16 MB fp16 transposed map (B,Hf,Wf,C)
__device__ float  g_depth[BNUM * HWIMG];            // 4 MB depth maps
__device__ float4 g_v3p[BNUM * NV];                 // float4-padded vertices3d
__device__ float2 g_ctr[NPT];                       // centers2d (coords -> geom)
__device__ uint4  g_wt4 [NPT];                      // packed half2x4 weights (orig order)
__device__ int    g_bin [NPT];                      // per-point bin id
__device__ int    g_ord [NPT];                      // sorted slot -> original point idx
__device__ int    g_hist[NBINS];                    // bin histogram
__device__ int    g_start[NBINS];                   // global exclusive bin starts
__device__ int    g_cursor[NBINS];                  // mutable cursors (perm) -> bin ends
__device__ int    g_bsum[NSBLK];                    // scan-block totals -> exclusive offsets

// ---------------------------------------------------------------------------
// Kernel 1 (main, CRITICAL PATH): zero the bin histogram only (256 KB).
// ---------------------------------------------------------------------------
__global__ void zero_hist_k() {
    const int i = blockIdx.x * blockDim.x + threadIdx.x;
    if (i < NBINS / 4)
        reinterpret_cast<int4*>(g_hist)[i] = make_int4(0, 0, 0, 0);
}

// ---------------------------------------------------------------------------
// Kernel A1b (aux): init depth (+inf) and pad v3d to float4 (only scatter /
// geom consume these -- off the critical path).
// ---------------------------------------------------------------------------
__global__ void init_pad_k(const float* __restrict__ v3d) {
    const int i = blockIdx.x * blockDim.x + threadIdx.x;
    if (i < BNUM * HWIMG / 4) {
        reinterpret_cast<float4*>(g_depth)[i] =
            make_float4(CUDART_INF_F, CUDART_INF_F, CUDART_INF_F, CUDART_INF_F);
    }
    if (i < BNUM * NV) {
        g_v3p[i] = make_float4(v3d[3 * i], v3d[3 * i + 1], v3d[3 * i + 2], 0.0f);
    }
}

// ---------------------------------------------------------------------------
// Kernel 2 (main, CRITICAL PATH): centers2d -> bilinear weights + bin + hist.
// Edge fold (proven R12): off-left/off-top weight mass moves onto the clamped
// corner so every nonzero weight matches the bin-decoded corner.
// ---------------------------------------------------------------------------
__global__ void coords_k(const float* __restrict__ v2d,
                         const int*   __restrict__ parents,
                         const float* __restrict__ bary) {
    const int idx = blockIdx.x * blockDim.x + threadIdx.x;
    if (idx >= NPT) return;
    const int b = idx / NPTS;
    const int n = idx - b * NPTS;
    const int kk = n % KB;

    const float w0 = __ldg(&bary[kk * 3 + 0]);
    const float w1 = __ldg(&bary[kk * 3 + 1]);
    const float w2 = __ldg(&bary[kk * 3 + 2]);

    const int p0 = __ldg(&parents[n * 3 + 0]);
    const int p1 = __ldg(&parents[n * 3 + 1]);
    const int p2 = __ldg(&parents[n * 3 + 2]);

    const float* v2b = v2d + (size_t)b * NV * 2;
    const float2 a2 = *reinterpret_cast<const float2*>(v2b + 2 * p0);
    const float2 b2 = *reinterpret_cast<const float2*>(v2b + 2 * p1);
    const float2 c2 = *reinterpret_cast<const float2*>(v2b + 2 * p2);
    const float cx = w0 * a2.x + w1 * b2.x + w2 * c2.x;
    const float cy = w0 * a2.y + w1 * b2.y + w2 * c2.y;

    g_ctr[idx] = make_float2(cx, cy);

    // grid-sample pixel coords -> bilinear params (reference formula chain)
    const float gxn = cx / (float)(IMW - 1) * 2.0f - 1.0f;
    const float gyn = cy / (float)(IMH - 1) * 2.0f - 1.0f;
    const float px = (gxn + 1.0f) * 0.5f * (float)(WF - 1);
    const float py = (gyn + 1.0f) * 0.5f * (float)(HF - 1);

    const float x0f = floorf(px), y0f = floorf(py);
    const float wx = px - x0f, wy = py - y0f;
    const int x0 = (int)x0f, y0 = (int)y0f;

    const bool ix0 = (x0 >= 0) && (x0 < WF);
    const bool ix1 = (x0 + 1 >= 0) && (x0 + 1 < WF);
    const bool iy0 = (y0 >= 0) && (y0 < HF);
    const bool iy1 = (y0 + 1 >= 0) && (y0 + 1 < HF);

    float w00 = (1.0f - wx) * (1.0f - wy) * (float)(ix0 && iy0);
    float w10 = wx * (1.0f - wy)          * (float)(ix1 && iy0);
    float w01 = (1.0f - wx) * wy          * (float)(ix0 && iy1);
    float w11 = wx * wy                   * (float)(ix1 && iy1);

    if (x0 < 0) { w00 = w10; w01 = w11; w10 = 0.0f; w11 = 0.0f; }
    if (y0 < 0) { w00 = w01; w10 = w11; w01 = 0.0f; w11 = 0.0f; }

    const int xc0 = min(max(x0, 0), WF - 1);
    const int yc0 = min(max(y0, 0), HF - 1);
    const int bin = b * HWF + yc0 * WF + xc0;

    uint4 wp;
    const __half2 h0 = __float2half2_rn(w00);
    const __half2 h1 = __float2half2_rn(w10);
    const __half2 h2 = __float2half2_rn(w01);
    const __half2 h3 = __float2half2_rn(w11);
    wp.x = *reinterpret_cast<const uint32_t*>(&h0);
    wp.y = *reinterpret_cast<const uint32_t*>(&h1);
    wp.z = *reinterpret_cast<const uint32_t*>(&h2);
    wp.w = *reinterpret_cast<const uint32_t*>(&h3);
    g_wt4[idx] = wp;
    g_bin[idx] = bin;
    atomicAdd(&g_hist[bin], 1);
}

// ---------------------------------------------------------------------------
// Kernel A2 (aux): scatter-min vertex depths. z > 0 so int-cmp == float-cmp.
// ---------------------------------------------------------------------------
__global__ void scatter_k(const float* __restrict__ v2d, const float* __restrict__ v3d) {
    const int i = blockIdx.x * blockDim.x + threadIdx.x;
    if (i >= BNUM * NV) return;
    const float xf = rintf(v2d[2 * i]);       // round-half-even, matches jnp.round
    const float yf = rintf(v2d[2 * i + 1]);
    const int xi = (int)xf, yi = (int)yf;
    if (xi < 0 || xi >= IMW || yi < 0 || yi >= IMH) return;
    const int b = i / NV;
    const float z = v3d[3 * i + 2];
    atomicMin(reinterpret_cast<int*>(&g_depth[b * HWIMG + yi * IMW + xi]),
              __float_as_int(z));
}

// ---------------------------------------------------------------------------
// Kernel A3 (aux, overlaps scan/perm/sample): 3D geometry outputs.
// ---------------------------------------------------------------------------
__global__ void geom_k(const int* __restrict__ parents, const float* __restrict__ bary,
                       float* __restrict__ out_vw, float* __restrict__ out_c3) {
    const int idx = blockIdx.x * blockDim.x + threadIdx.x;
    if (idx >= NPT) return;
    const int b = idx / NPTS;
    const int n = idx - b * NPTS;
    const int kk = n % KB;

    const float w0 = __ldg(&bary[kk * 3 + 0]);
    const float w1 = __ldg(&bary[kk * 3 + 1]);
    const float w2 = __ldg(&bary[kk * 3 + 2]);

    const int p0 = __ldg(&parents[n * 3 + 0]);
    const int p1 = __ldg(&parents[n * 3 + 1]);
    const int p2 = __ldg(&parents[n * 3 + 2]);

    const float4* v3b = g_v3p + b * NV;
    const float4 va = __ldg(&v3b[p0]);
    const float4 vb = __ldg(&v3b[p1]);
    const float4 vg = __ldg(&v3b[p2]);

    const float c3x = w0 * va.x + w1 * vb.x + w2 * vg.x;
    const float c3y = w0 * va.y + w1 * vb.y + w2 * vg.y;
    const float c3z = w0 * va.z + w1 * vb.z + w2 * vg.z;

    const float e1x = vb.x - va.x, e1y = vb.y - va.y, e1z = vb.z - va.z;
    const float e2x = vg.x - va.x, e2y = vg.y - va.y, e2z = vg.z - va.z;
    float nx = e1y * e2z - e1z * e2y;
    float ny = e1z * e2x - e1x * e2z;
    float nz = e1x * e2y - e1y * e2x;
    const float nrm = sqrtf(nx * nx + ny * ny + nz * nz) + 1e-8f;
    nx /= nrm; ny /= nrm; nz /= nrm;

    const float cl = sqrtf(c3x * c3x + c3y * c3y + c3z * c3z) + 1e-8f;
    const float vx = -c3x / cl, vy = -c3y / cl, vz = -c3z / cl;
    const float ang = fmaxf(nx * vx + ny * vy + nz * vz, 0.0f);

    const float2 c = g_ctr[idx];
    const int xc = min(max((int)rintf(c.x), 0), IMW - 1);
    const int yc = min(max((int)rintf(c.y), 0), IMH - 1);
    const float dsamp = g_depth[b * HWIMG + yc * IMW + xc];
    const bool vis = (c3z <= dsamp + 1e-3f) || isinf(dsamp);

    out_vw[idx] = vis ? ang : 0.0f;
    out_c3[(size_t)idx * 3 + 0] = c3x;
    out_c3[(size_t)idx * 3 + 1] = c3y;
    out_c3[(size_t)idx * 3 + 2] = c3z;
}

// ---------------------------------------------------------------------------
// Kernel 3 (main): block-local exclusive scan via warp shuffles (2 barriers
// instead of 20 -- replaces the 6us Hillis-Steele).
// ---------------------------------------------------------------------------
__global__ void __launch_bounds__(1024) prefix1_k() {
    __shared__ int wsum[32];
    const int t = threadIdx.x;
    const int bin = blockIdx.x * 1024 + t;
    const int lane = t & 31;
    const int wid = t >> 5;

    const int v = g_hist[bin];
    int inc = v;
#pragma unroll
    for (int off = 1; off < 32; off <<= 1) {
        const int u = __shfl_up_sync(0xFFFFFFFF, inc, off);
        if (lane >= off) inc += u;
    }
    if (lane == 31) wsum[wid] = inc;
    __syncthreads();
    if (wid == 0) {
        int s = wsum[lane];
#pragma unroll
        for (int off = 1; off < 32; off <<= 1) {
            const int u = __shfl_up_sync(0xFFFFFFFF, s, off);
            if (lane >= off) s += u;
        }
        wsum[lane] = s;
    }
    __syncthreads();
    const int woff = (wid == 0) ? 0 : wsum[wid - 1];
    g_start[bin] = woff + inc - v;           // exclusive within block
    if (t == 1023) g_bsum[blockIdx.x] = woff + inc;
}

// ---------------------------------------------------------------------------
// Kernel 4 (main): exclusive scan of 64 block totals (warp shuffles, 2 warps).
// ---------------------------------------------------------------------------
__global__ void prefix2_k() {
    __shared__ int s2[2];
    const int t = threadIdx.x;       // 64 threads
    const int lane = t & 31;
    const int wid = t >> 5;
    int v = g_bsum[t];
    int inc = v;
#pragma unroll
    for (int off = 1; off < 32; off <<= 1) {
        const int u = __shfl_up_sync(0xFFFFFFFF, inc, off);
        if (lane >= off) inc += u;
    }
    if (lane == 31) s2[wid] = inc;
    __syncthreads();
    const int woff = (wid == 1) ? s2[0] : 0;
    g_bsum[t] = woff + inc - v;              // exclusive
}

// ---------------------------------------------------------------------------
// Kernel 5 (main): globalize starts; init cursors.
// ---------------------------------------------------------------------------
__global__ void fix_k() {
    const int bin = blockIdx.x * blockDim.x + threadIdx.x;
    if (bin >= NBINS) return;
    const int v = g_start[bin] + g_bsum[bin >> 10];
    g_start[bin]  = v;
    g_cursor[bin] = v;
}

// ---------------------------------------------------------------------------
// Kernel 6 (main): counting-sort scatter of ONLY the original index (4B) --
// weights stay in g_wt4 and are fetched by sample via oidx (1 broadcast line).
// ---------------------------------------------------------------------------
__global__ void perm_k() {
    const int idx = blockIdx.x * blockDim.x + threadIdx.x;
    if (idx >= NPT) return;
    const int bin = g_bin[idx];
    const int slot = atomicAdd(&g_cursor[bin], 1);
    g_ord[slot] = idx;
}

// ---------------------------------------------------------------------------
// Kernel A1a (aux): vectorized transpose + fp16 convert (measured 13.3us).
// ---------------------------------------------------------------------------
__global__ void __launch_bounds__(256) transpose_k(const float* __restrict__ fm) {
    __shared__ float4 tile4[32][33];
    const int b  = blockIdx.z;
    const int p0 = blockIdx.x * 128;
    const int c0 = blockIdx.y * 32;
    const float4* src4 = reinterpret_cast<const float4*>(fm + (size_t)b * CCH * HWF);
    uint4* dst = g_fmTh + (size_t)b * HWF * C8;

    const int tx = threadIdx.x;
    const int ty = threadIdx.y;
    const int tid = ty * 32 + tx;

#pragma unroll
    for (int k = 0; k < 4; k++) {
        const int r = ty + 8 * k;
        tile4[r][tx] = src4[(size_t)(c0 + r) * (HWF / 4) + (p0 / 4) + tx];
    }
    __syncthreads();

    const float* tilef = reinterpret_cast<const float*>(tile4);  // row stride 132
#pragma unroll
    for (int it = 0; it < 2; it++) {
        const int e = tid + it * 256;
        const int pix = e >> 2;
        const int q = e & 3;
        uint4 o;
        uint32_t* ow = reinterpret_cast<uint32_t*>(&o);
#pragma unroll
        for (int h = 0; h < 4; h++) {
            const int c = q * 8 + h * 2;
            const __half2 hh = __floats2half2_rn(tilef[c * 132 + pix],
                                                 tilef[(c + 1) * 132 + pix]);
            ow[h] = *reinterpret_cast<const uint32_t*>(&hh);
        }
        dst[(size_t)(p0 + pix) * C8 + (c0 / 8) + q] = o;
    }
}

// ---------------------------------------------------------------------------
// Kernel 7 (main): warp-per-bin gather sampling (write-bound, ~97us).
// Weights now fetched via g_wt4[oidx] -- one broadcast L1 line per point.
// ---------------------------------------------------------------------------
__global__ void __launch_bounds__(256) sample_k(float* __restrict__ out_feats) {
    const int bin = blockIdx.x * 8 + (threadIdx.x >> 5);
    if (bin >= NBINS) return;
    const int lane = threadIdx.x & 31;

    const int start = g_start[bin];
    const int end   = g_cursor[bin];
    if (start >= end) return;

    const int p  = bin & (HWF - 1);
    const int x0 = p & (WF - 1);
    const int y0 = p >> 7;
    const int dx = (x0 < WF - 1) ? 1 : 0;
    const int dy = (y0 < HF - 1) ? WF : 0;

    const uint2* fm2 = reinterpret_cast<const uint2*>(g_fmTh);
    const uint2 c00 = __ldg(fm2 + (size_t)(bin)           * 32 + lane);
    const uint2 c10 = __ldg(fm2 + (size_t)(bin + dx)      * 32 + lane);
    const uint2 c01 = __ldg(fm2 + (size_t)(bin + dy)      * 32 + lane);
    const uint2 c11 = __ldg(fm2 + (size_t)(bin + dx + dy) * 32 + lane);

    const __half2 a00 = *reinterpret_cast<const __half2*>(&c00.x);
    const __half2 b00 = *reinterpret_cast<const __half2*>(&c00.y);
    const __half2 a10 = *reinterpret_cast<const __half2*>(&c10.x);
    const __half2 b10 = *reinterpret_cast<const __half2*>(&c10.y);
    const __half2 a01 = *reinterpret_cast<const __half2*>(&c01.x);
    const __half2 b01 = *reinterpret_cast<const __half2*>(&c01.y);
    const __half2 a11 = *reinterpret_cast<const __half2*>(&c11.x);
    const __half2 b11 = *reinterpret_cast<const __half2*>(&c11.y);

    for (int s = start; s < end; s++) {
        const int  oidx = __ldg(&g_ord[s]);
        const uint4 wp  = __ldg(&g_wt4[oidx]);   // broadcast: one line per point

        const __half2 W00 = *reinterpret_cast<const __half2*>(&wp.x);
        const __half2 W10 = *reinterpret_cast<const __half2*>(&wp.y);
        const __half2 W01 = *reinterpret_cast<const __half2*>(&wp.z);
        const __half2 W11 = *reinterpret_cast<const __half2*>(&wp.w);

        __half2 ra = __hmul2(a00, W00);
        ra = __hfma2(a10, W10, ra);
        ra = __hfma2(a01, W01, ra);
        ra = __hfma2(a11, W11, ra);
        __half2 rb = __hmul2(b00, W00);
        rb = __hfma2(b10, W10, rb);
        rb = __hfma2(b01, W01, rb);
        rb = __hfma2(b11, W11, rb);

        const float2 fa = __half22float2(ra);
        const float2 fb = __half22float2(rb);
        float4* outp = reinterpret_cast<float4*>(out_feats) + (size_t)oidx * (CCH / 4) + lane;
        *outp = make_float4(fa.x, fa.y, fb.x, fb.y);
    }
}

// ---------------------------------------------------------------------------
// Launch graph (aux joins back to stream 0 before return):
//   main: zero_hist -> coords -> prefix1 -> prefix2 -> fix -> perm
//         -> (wait ev_t) sample -> (wait ev_geom)  [join]
//   aux:  transpose (ev_t) -> init_pad -> scatter -> (wait ev_crd) geom (ev_geom)
// ---------------------------------------------------------------------------
extern "C" void kernel_launch(void* const* d_in, const int* in_sizes, int n_in,
                              void* d_out, int out_size) {
    const float* fm      = (const float*)d_in[0];
    const float* v2d     = (const float*)d_in[1];
    const float* v3d     = (const float*)d_in[2];
    const int*   parents = (const int*)  d_in[3];
    const float* bary    = (const float*)d_in[4];
    (void)in_sizes; (void)n_in; (void)out_size;

    float* out       = (float*)d_out;
    float* out_feats = out;                                    // (B,N,C)
    float* out_vw    = out + (size_t)BNUM * NPTS * CCH;        // (B,N)
    float* out_c3    = out_vw + (size_t)BNUM * NPTS;           // (B,N,3)

    static cudaStream_t aux = nullptr;
    static cudaEvent_t  ev_root = nullptr, ev_crd = nullptr,
                        ev_t = nullptr, ev_geom = nullptr;
    if (aux == nullptr) {
        cudaStreamCreateWithFlags(&aux, cudaStreamNonBlocking);
        cudaEventCreateWithFlags(&ev_root, cudaEventDisableTiming);
        cudaEventCreateWithFlags(&ev_crd,  cudaEventDisableTiming);
        cudaEventCreateWithFlags(&ev_t,    cudaEventDisableTiming);
        cudaEventCreateWithFlags(&ev_geom, cudaEventDisableTiming);
    }

    // fork
    cudaEventRecord(ev_root, 0);
    cudaStreamWaitEvent(aux, ev_root, 0);

    // aux: transpose, depth init + vertex pad, depth scatter
    transpose_k<<<dim3(HWF / 128, CCH / 32, BNUM), dim3(32, 8), 0, aux>>>(fm);
    cudaEventRecord(ev_t, aux);
    init_pad_k<<<(BNUM * HWIMG / 4 + 255) / 256, 256, 0, aux>>>(v3d);
    scatter_k<<<(BNUM * NV + 255) / 256, 256, 0, aux>>>(v2d, v3d);

    // main critical path: zero_hist -> coords -> scan -> perm
    zero_hist_k<<<NBINS / 4 / 256, 256>>>();
    coords_k<<<(NPT + 255) / 256, 256>>>(v2d, parents, bary);
    cudaEventRecord(ev_crd, 0);
    prefix1_k<<<NSBLK, 1024>>>();
    prefix2_k<<<1, NSBLK>>>();
    fix_k<<<NBINS / 256, 256>>>();
    perm_k<<<(NPT + 255) / 256, 256>>>();

    // aux: geometry (needs coords' centers + depth map)
    cudaStreamWaitEvent(aux, ev_crd, 0);
    geom_k<<<(NPT + 255) / 256, 256, 0, aux>>>(parents, bary, out_vw, out_c3);
    cudaEventRecord(ev_geom, aux);

    // main: sample needs transpose + sorted order
    cudaStreamWaitEvent(0, ev_t, 0);
    sample_k<<<NBINS / 8, 256>>>(out_feats);

    // join aux back into stream 0 (required for graph capture; free at runtime)
    cudaStreamWaitEvent(0, ev_geom, 0);
}

// round 16
// speedup vs baseline: 2.1736x; 1.0302x over previous
#include <cuda_runtime.h>
#include <cuda_fp16.h>
#include <math_constants.h>
#include <cstdint>

// Problem dimensions (deterministic from setup_inputs)
#define BNUM 4
#define CCH 128          // channels
#define HF 128           // feature map height
#define WF 128           // feature map width
#define NV 10475         // vertices
#define NPTS 200000      // gaussians
#define KB 20            // bary rows
#define IMH 512
#define IMW 512
#define HWIMG (IMH*IMW)
#define HWF (HF*WF)
#define C8 (CCH / 8)     // uint4 (8 halves) per pixel = 16
#define NPT (BNUM * NPTS)
#define NBINS (BNUM * HWF)   // 65536 top-left-pixel bins
#define NSBLK 64             // scan blocks (1024 bins each)

// Scratch (static device globals -- no allocation allowed).
// g_hist relies on zero-initialization at module load; every launch re-zeroes
// it at the END (aux stream) so the invariant holds across graph replays.
__device__ uint4  g_fmTh[(size_t)BNUM * HWF * C8];  // 16 MB fp16 transposed map (B,Hf,Wf,C)
__device__ float  g_depth[BNUM * HWIMG];            // 4 MB depth maps
__device__ float4 g_v3p[BNUM * NV];                 // float4-padded vertices3d
__device__ float2 g_ctr[NPT];                       // centers2d (coords -> geom)
__device__ uint4  g_wt4 [NPT];                      // packed half2x4 weights (orig order)
__device__ int    g_bin [NPT];                      // per-point bin id
__device__ int    g_ord [NPT];                      // sorted slot -> original point idx
__device__ int    g_hist[NBINS];                    // bin histogram (zero between launches)
__device__ int    g_start[NBINS];                   // global exclusive bin starts
__device__ int    g_cursor[NBINS];                  // mutable cursors (perm) -> bin ends
__device__ int    g_bsum[NSBLK];                    // raw per-scan-block totals

// ---------------------------------------------------------------------------
// Kernel AZ (aux, end of graph): re-zero histogram for the next replay.
// ---------------------------------------------------------------------------
__global__ void zero_hist_k() {
    const int i = blockIdx.x * blockDim.x + threadIdx.x;
    if (i < NBINS / 4)
        reinterpret_cast<int4*>(g_hist)[i] = make_int4(0, 0, 0, 0);
}

// ---------------------------------------------------------------------------
// Kernel A1b (aux): init depth (+inf) and pad v3d to float4.
// ---------------------------------------------------------------------------
__global__ void init_pad_k(const float* __restrict__ v3d) {
    const int i = blockIdx.x * blockDim.x + threadIdx.x;
    if (i < BNUM * HWIMG / 4) {
        reinterpret_cast<float4*>(g_depth)[i] =
            make_float4(CUDART_INF_F, CUDART_INF_F, CUDART_INF_F, CUDART_INF_F);
    }
    if (i < BNUM * NV) {
        g_v3p[i] = make_float4(v3d[3 * i], v3d[3 * i + 1], v3d[3 * i + 2], 0.0f);
    }
}

// ---------------------------------------------------------------------------
// Kernel 1 (main, CRITICAL PATH): centers2d -> bilinear weights + bin + hist.
// Edge fold (proven R12): off-left/off-top weight mass moves onto the clamped
// corner so every nonzero weight matches the bin-decoded corner.
// ---------------------------------------------------------------------------
__global__ void coords_k(const float* __restrict__ v2d,
                         const int*   __restrict__ parents,
                         const float* __restrict__ bary) {
    const int idx = blockIdx.x * blockDim.x + threadIdx.x;
    if (idx >= NPT) return;
    const int b = idx / NPTS;
    const int n = idx - b * NPTS;
    const int kk = n % KB;

    const float w0 = __ldg(&bary[kk * 3 + 0]);
    const float w1 = __ldg(&bary[kk * 3 + 1]);
    const float w2 = __ldg(&bary[kk * 3 + 2]);

    const int p0 = __ldg(&parents[n * 3 + 0]);
    const int p1 = __ldg(&parents[n * 3 + 1]);
    const int p2 = __ldg(&parents[n * 3 + 2]);

    const float* v2b = v2d + (size_t)b * NV * 2;
    const float2 a2 = *reinterpret_cast<const float2*>(v2b + 2 * p0);
    const float2 b2 = *reinterpret_cast<const float2*>(v2b + 2 * p1);
    const float2 c2 = *reinterpret_cast<const float2*>(v2b + 2 * p2);
    const float cx = w0 * a2.x + w1 * b2.x + w2 * c2.x;
    const float cy = w0 * a2.y + w1 * b2.y + w2 * c2.y;

    g_ctr[idx] = make_float2(cx, cy);

    // grid-sample pixel coords -> bilinear params (reference formula chain)
    const float gxn = cx / (float)(IMW - 1) * 2.0f - 1.0f;
    const float gyn = cy / (float)(IMH - 1) * 2.0f - 1.0f;
    const float px = (gxn + 1.0f) * 0.5f * (float)(WF - 1);
    const float py = (gyn + 1.0f) * 0.5f * (float)(HF - 1);

    const float x0f = floorf(px), y0f = floorf(py);
    const float wx = px - x0f, wy = py - y0f;
    const int x0 = (int)x0f, y0 = (int)y0f;

    const bool ix0 = (x0 >= 0) && (x0 < WF);
    const bool ix1 = (x0 + 1 >= 0) && (x0 + 1 < WF);
    const bool iy0 = (y0 >= 0) && (y0 < HF);
    const bool iy1 = (y0 + 1 >= 0) && (y0 + 1 < HF);

    float w00 = (1.0f - wx) * (1.0f - wy) * (float)(ix0 && iy0);
    float w10 = wx * (1.0f - wy)          * (float)(ix1 && iy0);
    float w01 = (1.0f - wx) * wy          * (float)(ix0 && iy1);
    float w11 = wx * wy                   * (float)(ix1 && iy1);

    if (x0 < 0) { w00 = w10; w01 = w11; w10 = 0.0f; w11 = 0.0f; }
    if (y0 < 0) { w00 = w01; w10 = w11; w01 = 0.0f; w11 = 0.0f; }

    const int xc0 = min(max(x0, 0), WF - 1);
    const int yc0 = min(max(y0, 0), HF - 1);
    const int bin = b * HWF + yc0 * WF + xc0;

    uint4 wp;
    const __half2 h0 = __float2half2_rn(w00);
    const __half2 h1 = __float2half2_rn(w10);
    const __half2 h2 = __float2half2_rn(w01);
    const __half2 h3 = __float2half2_rn(w11);
    wp.x = *reinterpret_cast<const uint32_t*>(&h0);
    wp.y = *reinterpret_cast<const uint32_t*>(&h1);
    wp.z = *reinterpret_cast<const uint32_t*>(&h2);
    wp.w = *reinterpret_cast<const uint32_t*>(&h3);
    g_wt4[idx] = wp;
    g_bin[idx] = bin;
    atomicAdd(&g_hist[bin], 1);
}

// ---------------------------------------------------------------------------
// Kernel A2 (aux): scatter-min vertex depths. z > 0 so int-cmp == float-cmp.
// ---------------------------------------------------------------------------
__global__ void scatter_k(const float* __restrict__ v2d, const float* __restrict__ v3d) {
    const int i = blockIdx.x * blockDim.x + threadIdx.x;
    if (i >= BNUM * NV) return;
    const float xf = rintf(v2d[2 * i]);       // round-half-even, matches jnp.round
    const float yf = rintf(v2d[2 * i + 1]);
    const int xi = (int)xf, yi = (int)yf;
    if (xi < 0 || xi >= IMW || yi < 0 || yi >= IMH) return;
    const int b = i / NV;
    const float z = v3d[3 * i + 2];
    atomicMin(reinterpret_cast<int*>(&g_depth[b * HWIMG + yi * IMW + xi]),
              __float_as_int(z));
}

// ---------------------------------------------------------------------------
// Kernel A3 (aux, overlaps scan/perm/sample): 3D geometry outputs.
// ---------------------------------------------------------------------------
__global__ void geom_k(const int* __restrict__ parents, const float* __restrict__ bary,
                       float* __restrict__ out_vw, float* __restrict__ out_c3) {
    const int idx = blockIdx.x * blockDim.x + threadIdx.x;
    if (idx >= NPT) return;
    const int b = idx / NPTS;
    const int n = idx - b * NPTS;
    const int kk = n % KB;

    const float w0 = __ldg(&bary[kk * 3 + 0]);
    const float w1 = __ldg(&bary[kk * 3 + 1]);
    const float w2 = __ldg(&bary[kk * 3 + 2]);

    const int p0 = __ldg(&parents[n * 3 + 0]);
    const int p1 = __ldg(&parents[n * 3 + 1]);
    const int p2 = __ldg(&parents[n * 3 + 2]);

    const float4* v3b = g_v3p + b * NV;
    const float4 va = __ldg(&v3b[p0]);
    const float4 vb = __ldg(&v3b[p1]);
    const float4 vg = __ldg(&v3b[p2]);

    const float c3x = w0 * va.x + w1 * vb.x + w2 * vg.x;
    const float c3y = w0 * va.y + w1 * vb.y + w2 * vg.y;
    const float c3z = w0 * va.z + w1 * vb.z + w2 * vg.z;

    const float e1x = vb.x - va.x, e1y = vb.y - va.y, e1z = vb.z - va.z;
    const float e2x = vg.x - va.x, e2y = vg.y - va.y, e2z = vg.z - va.z;
    float nx = e1y * e2z - e1z * e2y;
    float ny = e1z * e2x - e1x * e2z;
    float nz = e1x * e2y - e1y * e2x;
    const float nrm = sqrtf(nx * nx + ny * ny + nz * nz) + 1e-8f;
    nx /= nrm; ny /= nrm; nz /= nrm;

    const float cl = sqrtf(c3x * c3x + c3y * c3y + c3z * c3z) + 1e-8f;
    const float vx = -c3x / cl, vy = -c3y / cl, vz = -c3z / cl;
    const float ang = fmaxf(nx * vx + ny * vy + nz * vz, 0.0f);

    const float2 c = g_ctr[idx];
    const int xc = min(max((int)rintf(c.x), 0), IMW - 1);
    const int yc = min(max((int)rintf(c.y), 0), IMH - 1);
    const float dsamp = g_depth[b * HWIMG + yc * IMW + xc];
    const bool vis = (c3z <= dsamp + 1e-3f) || isinf(dsamp);

    out_vw[idx] = vis ? ang : 0.0f;
    out_c3[(size_t)idx * 3 + 0] = c3x;
    out_c3[(size_t)idx * 3 + 1] = c3y;
    out_c3[(size_t)idx * 3 + 2] = c3z;
}

// ---------------------------------------------------------------------------
// Kernel 2 (main): block-local exclusive scan via warp shuffles.
// Writes raw block totals to g_bsum (consumed by fix2_k's reduction).
// ---------------------------------------------------------------------------
__global__ void __launch_bounds__(1024) prefix1_k() {
    __shared__ int wsum[32];
    const int t = threadIdx.x;
    const int bin = blockIdx.x * 1024 + t;
    const int lane = t & 31;
    const int wid = t >> 5;

    const int v = g_hist[bin];
    int inc = v;
#pragma unroll
    for (int off = 1; off < 32; off <<= 1) {
        const int u = __shfl_up_sync(0xFFFFFFFF, inc, off);
        if (lane >= off) inc += u;
    }
    if (lane == 31) wsum[wid] = inc;
    __syncthreads();
    if (wid == 0) {
        int s = wsum[lane];
#pragma unroll
        for (int off = 1; off < 32; off <<= 1) {
            const int u = __shfl_up_sync(0xFFFFFFFF, s, off);
            if (lane >= off) s += u;
        }
        wsum[lane] = s;
    }
    __syncthreads();
    const int woff = (wid == 0) ? 0 : wsum[wid - 1];
    g_start[bin] = woff + inc - v;           // exclusive within block
    if (t == 1023) g_bsum[blockIdx.x] = woff + inc;   // raw block total
}

// ---------------------------------------------------------------------------
// Kernel 3 (main): fused cross-block offset + globalize (replaces
// prefix2_k + fix_k). 64 blocks; one warp reduces bsum[0..k-1] (<=2 elems
// per lane), then all 1024 threads globalize start/cursor for their bin.
// ---------------------------------------------------------------------------
__global__ void __launch_bounds__(1024) fix2_k() {
    __shared__ int off_s;
    const int k = blockIdx.x;        // scan block 0..63
    const int t = threadIdx.x;
    if (t < 32) {
        int s = 0;
        if (t < k)      s += g_bsum[t];
        if (t + 32 < k) s += g_bsum[t + 32];
#pragma unroll
        for (int o = 16; o > 0; o >>= 1) s += __shfl_down_sync(0xFFFFFFFF, s, o);
        if (t == 0) off_s = s;
    }
    __syncthreads();
    const int bin = k * 1024 + t;
    const int v = g_start[bin] + off_s;
    g_start[bin]  = v;
    g_cursor[bin] = v;
}

// ---------------------------------------------------------------------------
// Kernel 4 (main): counting-sort scatter of only the original index (4B).
// ---------------------------------------------------------------------------
__global__ void perm_k() {
    const int idx = blockIdx.x * blockDim.x + threadIdx.x;
    if (idx >= NPT) return;
    const int bin = g_bin[idx];
    const int slot = atomicAdd(&g_cursor[bin], 1);
    g_ord[slot] = idx;
}

// ---------------------------------------------------------------------------
// Kernel A1a (aux): vectorized transpose + fp16 convert (measured 13.3us).
// ---------------------------------------------------------------------------
__global__ void __launch_bounds__(256) transpose_k(const float* __restrict__ fm) {
    __shared__ float4 tile4[32][33];
    const int b  = blockIdx.z;
    const int p0 = blockIdx.x * 128;
    const int c0 = blockIdx.y * 32;
    const float4* src4 = reinterpret_cast<const float4*>(fm + (size_t)b * CCH * HWF);
    uint4* dst = g_fmTh + (size_t)b * HWF * C8;

    const int tx = threadIdx.x;
    const int ty = threadIdx.y;
    const int tid = ty * 32 + tx;

#pragma unroll
    for (int k = 0; k < 4; k++) {
        const int r = ty + 8 * k;
        tile4[r][tx] = src4[(size_t)(c0 + r) * (HWF / 4) + (p0 / 4) + tx];
    }
    __syncthreads();

    const float* tilef = reinterpret_cast<const float*>(tile4);  // row stride 132
#pragma unroll
    for (int it = 0; it < 2; it++) {
        const int e = tid + it * 256;
        const int pix = e >> 2;
        const int q = e & 3;
        uint4 o;
        uint32_t* ow = reinterpret_cast<uint32_t*>(&o);
#pragma unroll
        for (int h = 0; h < 4; h++) {
            const int c = q * 8 + h * 2;
            const __half2 hh = __floats2half2_rn(tilef[c * 132 + pix],
                                                 tilef[(c + 1) * 132 + pix]);
            ow[h] = *reinterpret_cast<const uint32_t*>(&hh);
        }
        dst[(size_t)(p0 + pix) * C8 + (c0 / 8) + q] = o;
    }
}

// ---------------------------------------------------------------------------
// Kernel 5 (main): warp-per-bin gather sampling (write-bound, ~97us).
// ---------------------------------------------------------------------------
__global__ void __launch_bounds__(256) sample_k(float* __restrict__ out_feats) {
    const int bin = blockIdx.x * 8 + (threadIdx.x >> 5);
    if (bin >= NBINS) return;
    const int lane = threadIdx.x & 31;

    const int start = g_start[bin];
    const int end   = g_cursor[bin];
    if (start >= end) return;

    const int p  = bin & (HWF - 1);
    const int x0 = p & (WF - 1);
    const int y0 = p >> 7;
    const int dx = (x0 < WF - 1) ? 1 : 0;
    const int dy = (y0 < HF - 1) ? WF : 0;

    const uint2* fm2 = reinterpret_cast<const uint2*>(g_fmTh);
    const uint2 c00 = __ldg(fm2 + (size_t)(bin)           * 32 + lane);
    const uint2 c10 = __ldg(fm2 + (size_t)(bin + dx)      * 32 + lane);
    const uint2 c01 = __ldg(fm2 + (size_t)(bin + dy)      * 32 + lane);
    const uint2 c11 = __ldg(fm2 + (size_t)(bin + dx + dy) * 32 + lane);

    const __half2 a00 = *reinterpret_cast<const __half2*>(&c00.x);
    const __half2 b00 = *reinterpret_cast<const __half2*>(&c00.y);
    const __half2 a10 = *reinterpret_cast<const __half2*>(&c10.x);
    const __half2 b10 = *reinterpret_cast<const __half2*>(&c10.y);
    const __half2 a01 = *reinterpret_cast<const __half2*>(&c01.x);
    const __half2 b01 = *reinterpret_cast<const __half2*>(&c01.y);
    const __half2 a11 = *reinterpret_cast<const __half2*>(&c11.x);
    const __half2 b11 = *reinterpret_cast<const __half2*>(&c11.y);

    for (int s = start; s < end; s++) {
        const int  oidx = __ldg(&g_ord[s]);
        const uint4 wp  = __ldg(&g_wt4[oidx]);   // broadcast: one line per point

        const __half2 W00 = *reinterpret_cast<const __half2*>(&wp.x);
        const __half2 W10 = *reinterpret_cast<const __half2*>(&wp.y);
        const __half2 W01 = *reinterpret_cast<const __half2*>(&wp.z);
        const __half2 W11 = *reinterpret_cast<const __half2*>(&wp.w);

        __half2 ra = __hmul2(a00, W00);
        ra = __hfma2(a10, W10, ra);
        ra = __hfma2(a01, W01, ra);
        ra = __hfma2(a11, W11, ra);
        __half2 rb = __hmul2(b00, W00);
        rb = __hfma2(b10, W10, rb);
        rb = __hfma2(b01, W01, rb);
        rb = __hfma2(b11, W11, rb);

        const float2 fa = __half22float2(ra);
        const float2 fb = __half22float2(rb);
        float4* outp = reinterpret_cast<float4*>(out_feats) + (size_t)oidx * (CCH / 4) + lane;
        *outp = make_float4(fa.x, fa.y, fb.x, fb.y);
    }
}

// ---------------------------------------------------------------------------
// Launch graph (aux joins back to stream 0 before return):
//   main: coords -> prefix1 (ev_p1) -> fix2 -> perm
//         -> (wait ev_t) sample -> (wait ev_aux)  [join]
//   aux:  transpose (ev_t) -> init_pad -> scatter -> (wait ev_crd) geom
//         -> (wait ev_p1) zero_hist (ev_aux)
// hist is zero at first call (static zero-init) and re-zeroed each launch
// AFTER prefix1 (its last reader), off the critical path.
// ---------------------------------------------------------------------------
extern "C" void kernel_launch(void* const* d_in, const int* in_sizes, int n_in,
                              void* d_out, int out_size) {
    const float* fm      = (const float*)d_in[0];
    const float* v2d     = (const float*)d_in[1];
    const float* v3d     = (const float*)d_in[2];
    const int*   parents = (const int*)  d_in[3];
    const float* bary    = (const float*)d_in[4];
    (void)in_sizes; (void)n_in; (void)out_size;

    float* out       = (float*)d_out;
    float* out_feats = out;                                    // (B,N,C)
    float* out_vw    = out + (size_t)BNUM * NPTS * CCH;        // (B,N)
    float* out_c3    = out_vw + (size_t)BNUM * NPTS;           // (B,N,3)

    static cudaStream_t aux = nullptr;
    static cudaEvent_t  ev_root = nullptr, ev_crd = nullptr, ev_p1 = nullptr,
                        ev_t = nullptr, ev_aux = nullptr;
    if (aux == nullptr) {
        cudaStreamCreateWithFlags(&aux, cudaStreamNonBlocking);
        cudaEventCreateWithFlags(&ev_root, cudaEventDisableTiming);
        cudaEventCreateWithFlags(&ev_crd,  cudaEventDisableTiming);
        cudaEventCreateWithFlags(&ev_p1,   cudaEventDisableTiming);
        cudaEventCreateWithFlags(&ev_t,    cudaEventDisableTiming);
        cudaEventCreateWithFlags(&ev_aux,  cudaEventDisableTiming);
    }

    // fork
    cudaEventRecord(ev_root, 0);
    cudaStreamWaitEvent(aux, ev_root, 0);

    // aux: transpose, depth init + vertex pad, depth scatter
    transpose_k<<<dim3(HWF / 128, CCH / 32, BNUM), dim3(32, 8), 0, aux>>>(fm);
    cudaEventRecord(ev_t, aux);
    init_pad_k<<<(BNUM * HWIMG / 4 + 255) / 256, 256, 0, aux>>>(v3d);
    scatter_k<<<(BNUM * NV + 255) / 256, 256, 0, aux>>>(v2d, v3d);

    // main critical path: coords -> prefix1 -> fix2 -> perm
    coords_k<<<(NPT + 255) / 256, 256>>>(v2d, parents, bary);
    cudaEventRecord(ev_crd, 0);
    prefix1_k<<<NSBLK, 1024>>>();
    cudaEventRecord(ev_p1, 0);
    fix2_k<<<NSBLK, 1024>>>();
    perm_k<<<(NPT + 255) / 256, 256>>>();

    // aux: geometry (needs coords' centers + depth map), then hist cleanup
    cudaStreamWaitEvent(aux, ev_crd, 0);
    geom_k<<<(NPT + 255) / 256, 256, 0, aux>>>(parents, bary, out_vw, out_c3);
    cudaStreamWaitEvent(aux, ev_p1, 0);
    zero_hist_k<<<NBINS / 4 / 256, 256, 0, aux>>>();
    cudaEventRecord(ev_aux, aux);

    // main: sample needs transpose + sorted order
    cudaStreamWaitEvent(0, ev_t, 0);
    sample_k<<<NBINS / 8, 256>>>(out_feats);

    // join aux back into stream 0 (required for graph capture; free at runtime)
    cudaStreamWaitEvent(0, ev_aux, 0);
}